// round 7
// baseline (speedup 1.0000x reference)
#include <cuda_runtime.h>
#include <cuda_bf16.h>
#include <math.h>

#define TT 256
#define BB 64
#define HH 1024
#define G4 4096
#define OUT_Y ((size_t)TT * BB * 2 * HH)

typedef unsigned int u32;
typedef __nv_bfloat16 bf16;

// ---------------- scratch ----------------
__device__ float g_pre[(size_t)2 * TT * BB * G4];          // 512MB
__device__ float g_c[2][2][BB * HH];
__device__ bf16 g_h_hi[2][2][BB * HH], g_h_lo[2][2][BB * HH];
__device__ bf16 g_Wih_hi[(size_t)2 * G4 * HH], g_Wih_lo[(size_t)2 * G4 * HH];
__device__ bf16 g_Whh_hi[(size_t)2 * G4 * HH], g_Whh_lo[(size_t)2 * G4 * HH];
__device__ bf16 g_x_hi[(size_t)TT * BB * HH], g_x_lo[(size_t)TT * BB * HH];
__device__ unsigned int g_bar;                              // step barrier

// ---------------- PTX helpers (sm_80-compatible) ----------------
__device__ __forceinline__ u32 s2u(const void* p) {
    u32 a;
    asm("{ .reg .u64 t; cvta.to.shared.u64 t, %1; cvt.u32.u64 %0, t; }" : "=r"(a) : "l"(p));
    return a;
}
__device__ __forceinline__ void cpa16(u32 d, const void* s) {
    asm volatile("cp.async.cg.shared.global [%0], [%1], 16;" :: "r"(d), "l"(s));
}
#define CP_COMMIT asm volatile("cp.async.commit_group;" ::: "memory")
#define CP_WAIT1  asm volatile("cp.async.wait_group 1;" ::: "memory")

__device__ __forceinline__ void ldsm4(u32& r0, u32& r1, u32& r2, u32& r3, u32 a) {
    asm volatile("ldmatrix.sync.aligned.m8n8.x4.shared.b16 {%0,%1,%2,%3}, [%4];"
                 : "=r"(r0), "=r"(r1), "=r"(r2), "=r"(r3) : "r"(a));
}
__device__ __forceinline__ void mma16816(float* c, const u32* a, const u32* b) {
    asm volatile(
        "mma.sync.aligned.m16n8k16.row.col.f32.bf16.bf16.f32 "
        "{%0,%1,%2,%3}, {%4,%5,%6,%7}, {%8,%9}, {%0,%1,%2,%3};"
        : "+f"(c[0]), "+f"(c[1]), "+f"(c[2]), "+f"(c[3])
        : "r"(a[0]), "r"(a[1]), "r"(a[2]), "r"(a[3]), "r"(b[0]), "r"(b[1]));
}
__device__ __forceinline__ u32 ld_acq(const unsigned int* p) {
    u32 v;
    asm volatile("ld.acquire.gpu.u32 %0, [%1];" : "=r"(v) : "l"(p) : "memory");
    return v;
}

// ---------------- split / init ----------------
__global__ void split_kernel(const float* __restrict__ src, int sel, size_t off, int n2) {
    int i = blockIdx.x * 256 + threadIdx.x;
    if (i >= n2) return;
    float2 v = ((const float2*)src)[i];
    bf16 h0b = __float2bfloat16_rn(v.x);
    bf16 h1b = __float2bfloat16_rn(v.y);
    bf16 l0b = __float2bfloat16_rn(v.x - __bfloat162float(h0b));
    bf16 l1b = __float2bfloat16_rn(v.y - __bfloat162float(h1b));
    bf16 *hi, *lo;
    if (sel == 0)      { hi = g_Wih_hi; lo = g_Wih_lo; }
    else if (sel == 1) { hi = g_Whh_hi; lo = g_Whh_lo; }
    else               { hi = g_x_hi;   lo = g_x_lo;   }
    ((__nv_bfloat162*)(hi + off))[i] = __nv_bfloat162(h0b, h1b);
    ((__nv_bfloat162*)(lo + off))[i] = __nv_bfloat162(l0b, l1b);
}

__global__ void init_state(const float* __restrict__ h0) {
    int i = blockIdx.x * blockDim.x + threadIdx.x;  // BB*HH threads
    if (i == 0) g_bar = 0;
    float v = h0[i];
    bf16 hb = __float2bfloat16_rn(v);
    bf16 lb = __float2bfloat16_rn(v - __bfloat162float(hb));
    g_h_hi[0][0][i] = hb; g_h_hi[1][0][i] = hb;
    g_h_lo[0][0][i] = lb; g_h_lo[1][0][i] = lb;
    g_c[0][0][i] = v; g_c[1][0][i] = v;
}

// ============================================================
// Precompute: g_pre = x @ W_ih^T + b_ih + b_hh  (3-term bf16 split)
// Block: M=64 rows (r=b*T+t), N=128 gate cols, K=1024 (32 stages of 32).
// 3-buffer cp.async pipeline, ONE syncthreads per stage.
// ============================================================
#define PC_STAGE 30720
__global__ __launch_bounds__(256) void precompute_mma(
    const float* __restrict__ bihf, const float* __restrict__ bhhf,
    const float* __restrict__ bihb, const float* __restrict__ bhhb)
{
    extern __shared__ char smem[];
    const u32 smem_u = s2u(smem);
    const int tid = threadIdx.x, lane = tid & 31, wid = tid >> 5;
    const int wm = wid >> 2, wn = wid & 3;
    const int c0 = blockIdx.x * 128, rb = blockIdx.y, dir = blockIdx.z;

    const bf16* __restrict__ Ah = g_x_hi + (size_t)rb * 64 * HH;
    const bf16* __restrict__ Al = g_x_lo + (size_t)rb * 64 * HH;
    const bf16* __restrict__ Bh = g_Wih_hi + ((size_t)dir * G4 + c0) * HH;
    const bf16* __restrict__ Bl = g_Wih_lo + ((size_t)dir * G4 + c0) * HH;

    float acc[2][4][4];
#pragma unroll
    for (int mi = 0; mi < 2; mi++)
#pragma unroll
        for (int nj = 0; nj < 4; nj++)
#pragma unroll
            for (int q = 0; q < 4; q++) acc[mi][nj][q] = 0.f;

#define PC_LOAD(st, buf) do { \
    int ko_ = (st) * 32; \
    u32 ab_ = smem_u + (buf) * PC_STAGE; \
    _Pragma("unroll") \
    for (int it = 0; it < 2; it++) { \
        int id = it * 256 + tid, row = id >> 2, c = id & 3; \
        const bf16* s_ = (row < 64 ? Ah + (size_t)row * HH \
                                   : Al + (size_t)(row - 64) * HH) + ko_ + c * 8; \
        cpa16(ab_ + row * 80 + c * 16, s_); \
    } \
    u32 bb_ = ab_ + 10240; \
    _Pragma("unroll") \
    for (int it = 0; it < 4; it++) { \
        int id = it * 256 + tid, row = id >> 2, c = id & 3; \
        int hl = row >> 7, r7 = row & 127; \
        const bf16* s_ = (hl ? Bl : Bh) + (size_t)r7 * HH + ko_ + c * 8; \
        cpa16(bb_ + row * 80 + c * 16, s_); \
    } \
} while (0)

    PC_LOAD(0, 0); CP_COMMIT;
    PC_LOAD(1, 1); CP_COMMIT;
    for (int st = 0; st < 32; st++) {
        CP_WAIT1;
        __syncthreads();
        if (st + 2 < 32) { int bf = (st + 2) % 3; PC_LOAD(st + 2, bf); }
        CP_COMMIT;
        const u32 abase = smem_u + (st % 3) * PC_STAGE;
        const u32 bbase = abase + 10240;
#pragma unroll
        for (int kk = 0; kk < 2; kk++) {
            u32 a[2][2][4];
#pragma unroll
            for (int hl = 0; hl < 2; hl++)
#pragma unroll
                for (int mi = 0; mi < 2; mi++) {
                    int row = hl * 64 + wm * 32 + mi * 16 + (lane & 15);
                    ldsm4(a[hl][mi][0], a[hl][mi][1], a[hl][mi][2], a[hl][mi][3],
                          abase + row * 80 + kk * 32 + (lane >> 4) * 16);
                }
            u32 b_[2][4][2];
#pragma unroll
            for (int hl = 0; hl < 2; hl++)
#pragma unroll
                for (int nj2 = 0; nj2 < 2; nj2++) {
                    int row = hl * 128 + wn * 32 + nj2 * 16 + (lane & 7) + ((lane >> 4) << 3);
                    u32 r0, r1, r2, r3;
                    ldsm4(r0, r1, r2, r3,
                          bbase + row * 80 + kk * 32 + ((lane >> 3) & 1) * 16);
                    b_[hl][nj2 * 2][0] = r0; b_[hl][nj2 * 2][1] = r1;
                    b_[hl][nj2 * 2 + 1][0] = r2; b_[hl][nj2 * 2 + 1][1] = r3;
                }
#pragma unroll
            for (int mi = 0; mi < 2; mi++)
#pragma unroll
                for (int nj = 0; nj < 4; nj++) {
                    mma16816(acc[mi][nj], a[0][mi], b_[0][nj]);  // hi*hi
                    mma16816(acc[mi][nj], a[0][mi], b_[1][nj]);  // hi*lo
                    mma16816(acc[mi][nj], a[1][mi], b_[0][nj]);  // lo*hi
                }
        }
    }
#undef PC_LOAD

    const float* bi = dir ? bihb : bihf;
    const float* bh = dir ? bhhb : bhhf;
#pragma unroll
    for (int nj = 0; nj < 4; nj++) {
        int n = c0 + wn * 32 + nj * 8 + (lane & 3) * 2;
        float bz0 = bi[n] + bh[n];
        float bz1 = bi[n + 1] + bh[n + 1];
#pragma unroll
        for (int mi = 0; mi < 2; mi++)
#pragma unroll
            for (int hrow = 0; hrow < 2; hrow++) {
                int m = wm * 32 + mi * 16 + (lane >> 2) + hrow * 8;
                int r = rb * 64 + m, t = r & (TT - 1), bb2 = r >> 8;
                float* dst = g_pre + (((size_t)dir * TT + t) * BB + bb2) * G4 + n;
                float2 o;
                o.x = acc[mi][nj][hrow * 2 + 0] + bz0;
                o.y = acc[mi][nj][hrow * 2 + 1] + bz1;
                *(float2*)dst = o;
            }
    }
}

// ============================================================
// Persistent fused LSTM: ONE kernel runs all 256 steps.
// Grid = 128 CTAs (64 j-tiles x 2 dirs), all co-resident (1 CTA/SM).
// Per step: GEMM (M=64, N=64 gate cols, K=1024, 3-term bf16 split) ->
// smem fold -> pointwise update -> device-wide barrier.
// smem: 3 pipeline buffers (20480 each) + fold (64x72 f32).
// ============================================================
#define ST_STAGE 20480
#define SM_FOLD_OFF (3 * ST_STAGE)
#define ST_SMEM (3 * ST_STAGE + 64 * 72 * 4)
#define NCTA 128

__global__ __launch_bounds__(256, 1) void step_persist(
    const int* __restrict__ mask, const float* __restrict__ h0,
    float* __restrict__ out)
{
    extern __shared__ char smem[];
    const u32 smem_u = s2u(smem);
    const int tid = threadIdx.x, lane = tid & 31, wid = tid >> 5;
    const int wm = wid >> 1, wn = wid & 1;
    const int j0 = blockIdx.x * 16, dir = blockIdx.y;

    const bf16* __restrict__ Wh = g_Whh_hi + (size_t)dir * G4 * HH;
    const bf16* __restrict__ Wl = g_Whh_lo + (size_t)dir * G4 * HH;
    float* fold = (float*)(smem + SM_FOLD_OFF);

    for (int s = 0; s < TT; s++) {
        const int pp = s & 1;
        const int t = dir ? (TT - 1 - s) : s;
        const bf16* __restrict__ Ah = g_h_hi[dir][pp];
        const bf16* __restrict__ Al = g_h_lo[dir][pp];

        float acc[4][4];
#pragma unroll
        for (int nj = 0; nj < 4; nj++)
#pragma unroll
            for (int q = 0; q < 4; q++) acc[nj][q] = 0.f;

#define ST_LOAD(st, buf) do { \
    int ko_ = (st) * 32; \
    u32 ab_ = smem_u + (buf) * ST_STAGE; \
    _Pragma("unroll") \
    for (int it = 0; it < 2; it++) { \
        int id = it * 256 + tid, row = id >> 2, c = id & 3; \
        const bf16* s_ = (row < 64 ? Ah + (size_t)row * HH \
                                   : Al + (size_t)(row - 64) * HH) + ko_ + c * 8; \
        cpa16(ab_ + row * 80 + c * 16, s_); \
    } \
    u32 bb_ = ab_ + 10240; \
    _Pragma("unroll") \
    for (int it = 0; it < 2; it++) { \
        int id = it * 256 + tid, row = id >> 2, c = id & 3; \
        int hl = row >> 6, r6 = row & 63, grp = r6 >> 4, jj = r6 & 15; \
        const bf16* s_ = (hl ? Wl : Wh) + (size_t)(grp * HH + j0 + jj) * HH + ko_ + c * 8; \
        cpa16(bb_ + row * 80 + c * 16, s_); \
    } \
} while (0)

        ST_LOAD(0, 0); CP_COMMIT;
        ST_LOAD(1, 1); CP_COMMIT;
        for (int st = 0; st < 32; st++) {
            CP_WAIT1;
            __syncthreads();
            if (st + 2 < 32) { int bf = (st + 2) % 3; ST_LOAD(st + 2, bf); }
            CP_COMMIT;
            const u32 abase = smem_u + (st % 3) * ST_STAGE;
            const u32 bbase = abase + 10240;
#pragma unroll
            for (int kk = 0; kk < 2; kk++) {
                u32 a[2][4];
#pragma unroll
                for (int hl = 0; hl < 2; hl++) {
                    int row = hl * 64 + wm * 16 + (lane & 15);
                    ldsm4(a[hl][0], a[hl][1], a[hl][2], a[hl][3],
                          abase + row * 80 + kk * 32 + (lane >> 4) * 16);
                }
                u32 b_[2][4][2];
#pragma unroll
                for (int hl = 0; hl < 2; hl++)
#pragma unroll
                    for (int nj2 = 0; nj2 < 2; nj2++) {
                        int row = hl * 64 + wn * 32 + nj2 * 16 + (lane & 7) + ((lane >> 4) << 3);
                        u32 r0, r1, r2, r3;
                        ldsm4(r0, r1, r2, r3,
                              bbase + row * 80 + kk * 32 + ((lane >> 3) & 1) * 16);
                        b_[hl][nj2 * 2][0] = r0; b_[hl][nj2 * 2][1] = r1;
                        b_[hl][nj2 * 2 + 1][0] = r2; b_[hl][nj2 * 2 + 1][1] = r3;
                    }
#pragma unroll
                for (int nj = 0; nj < 4; nj++) {
                    mma16816(acc[nj], a[0], b_[0][nj]);  // hi*hi
                    mma16816(acc[nj], a[0], b_[1][nj]);  // hi*lo
                    mma16816(acc[nj], a[1], b_[0][nj]);  // lo*hi
                }
            }
        }
#undef ST_LOAD

        // ---- fold accumulators into smem [64 batches][64 gate cols] ----
        __syncthreads();   // all MMA smem reads done before fold reuse? (fold is separate region; this orders acc writes vs reads below)
#pragma unroll
        for (int nj = 0; nj < 4; nj++) {
            int n = wn * 32 + nj * 8 + (lane & 3) * 2;
            int m = wm * 16 + (lane >> 2);
            *(float2*)&fold[m * 72 + n]       = make_float2(acc[nj][0], acc[nj][1]);
            *(float2*)&fold[(m + 8) * 72 + n] = make_float2(acc[nj][2], acc[nj][3]);
        }
        __syncthreads();

        // ---- pointwise: 64 b x 16 jj outputs ----
#pragma unroll
        for (int it = 0; it < 4; it++) {
            int id = it * 256 + tid;
            int b = id >> 4, jj = id & 15;
            int j = j0 + jj;
            const float* pre = g_pre + (((size_t)dir * TT + t) * BB + b) * G4;
            float gi = fold[b * 72 + jj]      + pre[j];
            float gf = fold[b * 72 + 16 + jj] + pre[HH + j];
            float gg = fold[b * 72 + 32 + jj] + pre[2 * HH + j];
            float go = fold[b * 72 + 48 + jj] + pre[3 * HH + j];
            float iv = 1.f / (1.f + expf(-gi));
            float fv = 1.f / (1.f + expf(-gf));
            float gv = tanhf(gg);
            float ov = 1.f / (1.f + expf(-go));
            float cn = fv * g_c[dir][pp][b * HH + j] + iv * gv;
            float hn = ov * tanhf(cn);
            float m = (float)mask[b * TT + t];
            float hz = h0[b * HH + j];
            hn = hn * m + hz * (1.f - m);
            cn = cn * m + hz * (1.f - m);
            g_c[dir][pp ^ 1][b * HH + j] = cn;
            bf16 hh = __float2bfloat16_rn(hn);
            g_h_hi[dir][pp ^ 1][b * HH + j] = hh;
            g_h_lo[dir][pp ^ 1][b * HH + j] = __float2bfloat16_rn(hn - __bfloat162float(hh));
            // outputs stacked in ITERATION order for both directions (per reference)
            out[((size_t)s * BB + b) * (2 * HH) + (size_t)dir * HH + j] = hn;
            if (s == TT - 1) {
                out[OUT_Y + (size_t)b * (2 * HH) + (size_t)dir * HH + j] = hn;
                out[OUT_Y + (size_t)BB * 2 * HH + (size_t)b * (2 * HH) + (size_t)dir * HH + j] = cn;
            }
        }

        // ---- device-wide barrier (skip after last step) ----
        if (s < TT - 1) {
            __threadfence();
            __syncthreads();
            if (tid == 0) {
                atomicAdd(&g_bar, 1u);
                unsigned int target = (unsigned int)NCTA * (s + 1);
                while (ld_acq(&g_bar) < target) { }
            }
            __syncthreads();
        }
    }
}

// ---------------- host ----------------
extern "C" void kernel_launch(void* const* d_in, const int* in_sizes, int n_in,
                              void* d_out, int out_size) {
    const float* x    = (const float*)d_in[0];
    const int*   mask = (const int*)  d_in[1];
    const float* h0   = (const float*)d_in[2];
    const float* Wihf = (const float*)d_in[3];
    const float* Whhf = (const float*)d_in[4];
    const float* bihf = (const float*)d_in[5];
    const float* bhhf = (const float*)d_in[6];
    const float* Wihb = (const float*)d_in[7];
    const float* Whhb = (const float*)d_in[8];
    const float* bihb = (const float*)d_in[9];
    const float* bhhb = (const float*)d_in[10];
    float* out = (float*)d_out;

    cudaFuncSetAttribute(precompute_mma, cudaFuncAttributeMaxDynamicSharedMemorySize, 3 * PC_STAGE);
    cudaFuncSetAttribute(step_persist,   cudaFuncAttributeMaxDynamicSharedMemorySize, ST_SMEM);

    const size_t WOFF = (size_t)G4 * HH;
    split_kernel<<<8192, 256>>>(Wihf, 0, 0,    2097152);
    split_kernel<<<8192, 256>>>(Wihb, 0, WOFF, 2097152);
    split_kernel<<<8192, 256>>>(Whhf, 1, 0,    2097152);
    split_kernel<<<8192, 256>>>(Whhb, 1, WOFF, 2097152);
    split_kernel<<<32768, 256>>>(x,   2, 0,    8388608);
    init_state<<<(BB * HH) / 256, 256>>>(h0);

    precompute_mma<<<dim3(32, 256, 2), 256, 3 * PC_STAGE>>>(bihf, bhhf, bihb, bhhb);

    step_persist<<<dim3(64, 2), 256, ST_SMEM>>>(mask, h0, out);
}

// round 9
// speedup vs baseline: 1.5828x; 1.5828x over previous
#include <cuda_runtime.h>
#include <cuda_fp16.h>
#include <math.h>

#define TT 256
#define BB 64
#define HH 1024
#define G4 4096
#define OUT_Y ((size_t)TT * BB * 2 * HH)

typedef unsigned int u32;

// ---------------- scratch ----------------
__device__ float g_pre[(size_t)2 * TT * BB * G4];          // 512MB
__device__ __half g_h_hi[2][2][BB * HH], g_h_lo[2][2][BB * HH];
__device__ __half g_Wih_hi[(size_t)2 * G4 * HH], g_Wih_lo[(size_t)2 * G4 * HH];
__device__ __half g_Whh16[(size_t)2 * G4 * HH];
__device__ __half g_x_hi[(size_t)TT * BB * HH], g_x_lo[(size_t)TT * BB * HH];
__device__ unsigned int g_bar2[2];

// ---------------- PTX helpers ----------------
__device__ __forceinline__ u32 s2u(const void* p) {
    u32 a;
    asm("{ .reg .u64 t; cvta.to.shared.u64 t, %1; cvt.u32.u64 %0, t; }" : "=r"(a) : "l"(p));
    return a;
}
__device__ __forceinline__ void cpa16(u32 d, const void* s) {
    asm volatile("cp.async.cg.shared.global [%0], [%1], 16;" :: "r"(d), "l"(s));
}
#define CP_COMMIT asm volatile("cp.async.commit_group;" ::: "memory")
#define CP_WAIT1  asm volatile("cp.async.wait_group 1;" ::: "memory")

__device__ __forceinline__ void ldsm4(u32& r0, u32& r1, u32& r2, u32& r3, u32 a) {
    asm volatile("ldmatrix.sync.aligned.m8n8.x4.shared.b16 {%0,%1,%2,%3}, [%4];"
                 : "=r"(r0), "=r"(r1), "=r"(r2), "=r"(r3) : "r"(a));
}
__device__ __forceinline__ void mma16816(float* c, const u32* a, const u32* b) {
    asm volatile(
        "mma.sync.aligned.m16n8k16.row.col.f32.f16.f16.f32 "
        "{%0,%1,%2,%3}, {%4,%5,%6,%7}, {%8,%9}, {%0,%1,%2,%3};"
        : "+f"(c[0]), "+f"(c[1]), "+f"(c[2]), "+f"(c[3])
        : "r"(a[0]), "r"(a[1]), "r"(a[2]), "r"(a[3]), "r"(b[0]), "r"(b[1]));
}
__device__ __forceinline__ u32 ld_acq(const unsigned int* p) {
    u32 v;
    asm volatile("ld.acquire.gpu.u32 %0, [%1];" : "=r"(v) : "l"(p) : "memory");
    return v;
}

// ---------------- split / init ----------------
__global__ void split_pair(const float* __restrict__ src, int sel, size_t off, int n2) {
    int i = blockIdx.x * 256 + threadIdx.x;
    if (i >= n2) return;
    float2 v = ((const float2*)src)[i];
    __half h0v = __float2half_rn(v.x);
    __half h1v = __float2half_rn(v.y);
    __half l0v = __float2half_rn(v.x - __half2float(h0v));
    __half l1v = __float2half_rn(v.y - __half2float(h1v));
    __half *hi, *lo;
    if (sel == 0) { hi = g_Wih_hi; lo = g_Wih_lo; }
    else          { hi = g_x_hi;   lo = g_x_lo;   }
    ((__half2*)(hi + off))[i] = __halves2half2(h0v, h1v);
    ((__half2*)(lo + off))[i] = __halves2half2(l0v, l1v);
}

__global__ void split_one(const float* __restrict__ src, size_t off, int n2) {
    int i = blockIdx.x * 256 + threadIdx.x;
    if (i >= n2) return;
    float2 v = ((const float2*)src)[i];
    ((__half2*)(g_Whh16 + off))[i] =
        __halves2half2(__float2half_rn(v.x), __float2half_rn(v.y));
}

__global__ void init_state(const float* __restrict__ h0) {
    int i = blockIdx.x * blockDim.x + threadIdx.x;  // BB*HH threads
    if (i == 0) { g_bar2[0] = 0; g_bar2[1] = 0; }
    float v = h0[i];
    __half hb = __float2half_rn(v);
    __half lb = __float2half_rn(v - __half2float(hb));
    g_h_hi[0][0][i] = hb; g_h_hi[1][0][i] = hb;
    g_h_lo[0][0][i] = lb; g_h_lo[1][0][i] = lb;
}

// ============================================================
// Precompute: g_pre = x @ W_ih^T + b_ih + b_hh  (3-term fp16 split)
// Block: M=64 rows (r=b*T+t), N=128 gate cols, K=1024 (32 stages of 32).
// ============================================================
#define PC_STAGE 30720
__global__ __launch_bounds__(256, 2) void precompute_mma(
    const float* __restrict__ bihf, const float* __restrict__ bhhf,
    const float* __restrict__ bihb, const float* __restrict__ bhhb)
{
    extern __shared__ char smem[];
    const u32 smem_u = s2u(smem);
    const int tid = threadIdx.x, lane = tid & 31, wid = tid >> 5;
    const int wm = wid >> 2, wn = wid & 3;
    const int c0 = blockIdx.x * 128, rb = blockIdx.y, dir = blockIdx.z;

    const __half* __restrict__ Ah = g_x_hi + (size_t)rb * 64 * HH;
    const __half* __restrict__ Al = g_x_lo + (size_t)rb * 64 * HH;
    const __half* __restrict__ Bh = g_Wih_hi + ((size_t)dir * G4 + c0) * HH;
    const __half* __restrict__ Bl = g_Wih_lo + ((size_t)dir * G4 + c0) * HH;

    float acc[2][4][4];
#pragma unroll
    for (int mi = 0; mi < 2; mi++)
#pragma unroll
        for (int nj = 0; nj < 4; nj++)
#pragma unroll
            for (int q = 0; q < 4; q++) acc[mi][nj][q] = 0.f;

#define PC_LOAD(st, buf) do { \
    int ko_ = (st) * 32; \
    u32 ab_ = smem_u + (buf) * PC_STAGE; \
    _Pragma("unroll") \
    for (int it = 0; it < 2; it++) { \
        int id = it * 256 + tid, row = id >> 2, c = id & 3; \
        const __half* s_ = (row < 64 ? Ah + (size_t)row * HH \
                                     : Al + (size_t)(row - 64) * HH) + ko_ + c * 8; \
        cpa16(ab_ + row * 80 + c * 16, s_); \
    } \
    u32 bb_ = ab_ + 10240; \
    _Pragma("unroll") \
    for (int it = 0; it < 4; it++) { \
        int id = it * 256 + tid, row = id >> 2, c = id & 3; \
        int hl = row >> 7, r7 = row & 127; \
        const __half* s_ = (hl ? Bl : Bh) + (size_t)r7 * HH + ko_ + c * 8; \
        cpa16(bb_ + row * 80 + c * 16, s_); \
    } \
} while (0)

    PC_LOAD(0, 0); CP_COMMIT;
    PC_LOAD(1, 1); CP_COMMIT;
    for (int st = 0; st < 32; st++) {
        CP_WAIT1;
        __syncthreads();
        if (st + 2 < 32) { int bf = (st + 2) % 3; PC_LOAD(st + 2, bf); }
        CP_COMMIT;
        const u32 abase = smem_u + (st % 3) * PC_STAGE;
        const u32 bbase = abase + 10240;
#pragma unroll
        for (int kk = 0; kk < 2; kk++) {
            u32 a[2][2][4];
#pragma unroll
            for (int hl = 0; hl < 2; hl++)
#pragma unroll
                for (int mi = 0; mi < 2; mi++) {
                    int row = hl * 64 + wm * 32 + mi * 16 + (lane & 15);
                    ldsm4(a[hl][mi][0], a[hl][mi][1], a[hl][mi][2], a[hl][mi][3],
                          abase + row * 80 + kk * 32 + (lane >> 4) * 16);
                }
            u32 b_[2][4][2];
#pragma unroll
            for (int hl = 0; hl < 2; hl++)
#pragma unroll
                for (int nj2 = 0; nj2 < 2; nj2++) {
                    int row = hl * 128 + wn * 32 + nj2 * 16 + (lane & 7) + ((lane >> 4) << 3);
                    u32 r0, r1, r2, r3;
                    ldsm4(r0, r1, r2, r3,
                          bbase + row * 80 + kk * 32 + ((lane >> 3) & 1) * 16);
                    b_[hl][nj2 * 2][0] = r0; b_[hl][nj2 * 2][1] = r1;
                    b_[hl][nj2 * 2 + 1][0] = r2; b_[hl][nj2 * 2 + 1][1] = r3;
                }
#pragma unroll
            for (int mi = 0; mi < 2; mi++)
#pragma unroll
                for (int nj = 0; nj < 4; nj++) {
                    mma16816(acc[mi][nj], a[0][mi], b_[0][nj]);  // hi*hi
                    mma16816(acc[mi][nj], a[0][mi], b_[1][nj]);  // hi*lo
                    mma16816(acc[mi][nj], a[1][mi], b_[0][nj]);  // lo*hi
                }
        }
    }
#undef PC_LOAD

    const float* bi = dir ? bihb : bihf;
    const float* bh = dir ? bhhb : bhhf;
#pragma unroll
    for (int nj = 0; nj < 4; nj++) {
        int n = c0 + wn * 32 + nj * 8 + (lane & 3) * 2;
        float bz0 = bi[n] + bh[n];
        float bz1 = bi[n + 1] + bh[n + 1];
#pragma unroll
        for (int mi = 0; mi < 2; mi++)
#pragma unroll
            for (int hrow = 0; hrow < 2; hrow++) {
                int m = wm * 32 + mi * 16 + (lane >> 2) + hrow * 8;
                int r = rb * 64 + m, t = r & (TT - 1), bb2 = r >> 8;
                float* dst = g_pre + (((size_t)dir * TT + t) * BB + bb2) * G4 + n;
                float2 o;
                o.x = acc[mi][nj][hrow * 2 + 0] + bz0;
                o.y = acc[mi][nj][hrow * 2 + 1] + bz1;
                *(float2*)dst = o;
            }
    }
}

// ============================================================
// Persistent fused LSTM. 128 CTAs (64 j-tiles x 2 dirs), 1/SM.
// W_hh slice (64 gate-cols x 1024 k, single fp16) RESIDENT in smem.
// Per step: stream h hi/lo (2-term exact GEMM) -> gates -> pointwise.
// c lives in registers. Per-dir spin barrier between steps.
// smem: W 132096 | A 3x10240 | gates 64x68 f32 | pre 64x68 f32
// ============================================================
#define W_STR 2064
#define A_OFF 132096
#define A_STAGE 10240
#define GATES_OFF 162816
#define PRE_OFF 180224
#define ST_SMEM 197632

__global__ __launch_bounds__(256, 1) void step_persist(
    const int* __restrict__ mask, const float* __restrict__ h0,
    float* __restrict__ out)
{
    extern __shared__ char smem[];
    const u32 smem_u = s2u(smem);
    const int tid = threadIdx.x, lane = tid & 31, wid = tid >> 5;
    const int wm = wid >> 1, wn = wid & 1;
    const int j0 = blockIdx.x * 16, dir = blockIdx.y;

    // ---- load resident W (64 gate-cols x 1024 k fp16) ----
    {
        const __half* W = g_Whh16 + (size_t)dir * G4 * HH;
#pragma unroll
        for (int it = 0; it < 32; it++) {
            int id = it * 256 + tid;
            int row = id >> 7, c = id & 127;       // row: gate-col, c: 16B chunk
            int grp = row >> 4, jj = row & 15;
            cpa16(smem_u + row * W_STR + c * 16,
                  W + (size_t)(grp * HH + j0 + jj) * HH + c * 8);
        }
        CP_COMMIT;
    }

    // ---- per-thread persistent state: h0 cache + c registers ----
    float h0c[4], creg[4];
#pragma unroll
    for (int it = 0; it < 4; it++) {
        int id = it * 256 + tid;
        int b = id >> 4, jj = id & 15;
        h0c[it] = h0[b * HH + j0 + jj];
        creg[it] = h0c[it];
    }

    float* gates = (float*)(smem + GATES_OFF);
    const float* presm = (const float*)(smem + PRE_OFF);

    for (int s = 0; s < TT; s++) {
        const int pp = s & 1;
        const int t = dir ? (TT - 1 - s) : s;
        const __half* __restrict__ Ah = g_h_hi[dir][pp];
        const __half* __restrict__ Al = g_h_lo[dir][pp];
        const float* __restrict__ preg = g_pre + ((size_t)dir * TT + t) * BB * G4;

        float acc[4][4];
#pragma unroll
        for (int nj = 0; nj < 4; nj++)
#pragma unroll
            for (int q = 0; q < 4; q++) acc[nj][q] = 0.f;

#define ST_LOAD(st, buf) do { \
    int ko_ = (st) * 32; \
    u32 ab_ = smem_u + A_OFF + (buf) * A_STAGE; \
    _Pragma("unroll") \
    for (int it = 0; it < 2; it++) { \
        int id = it * 256 + tid, row = id >> 2, c = id & 3; \
        const __half* s_ = (row < 64 ? Ah + (size_t)row * HH \
                                     : Al + (size_t)(row - 64) * HH) + ko_ + c * 8; \
        cpa16(ab_ + row * 80 + c * 16, s_); \
    } \
} while (0)

        // stage 0 + pre-gate tile prefetch in one group
        ST_LOAD(0, 0);
#pragma unroll
        for (int it = 0; it < 4; it++) {
            int id = it * 256 + tid;
            int b = id >> 4, seg = (id >> 2) & 3, q = id & 3;
            cpa16(smem_u + PRE_OFF + b * 272 + seg * 64 + q * 16,
                  preg + (size_t)b * G4 + seg * HH + j0 + q * 4);
        }
        CP_COMMIT;
        ST_LOAD(1, 1); CP_COMMIT;

        for (int st = 0; st < 32; st++) {
            CP_WAIT1;
            __syncthreads();
            if (st + 2 < 32) { int bf = (st + 2) % 3; ST_LOAD(st + 2, bf); }
            CP_COMMIT;
            const u32 abase = smem_u + A_OFF + (st % 3) * A_STAGE;
            const u32 wkoff = st * 64;
#pragma unroll
            for (int kk = 0; kk < 2; kk++) {
                u32 a[2][4];
#pragma unroll
                for (int hl = 0; hl < 2; hl++) {
                    int row = hl * 64 + wm * 16 + (lane & 15);
                    ldsm4(a[hl][0], a[hl][1], a[hl][2], a[hl][3],
                          abase + row * 80 + kk * 32 + (lane >> 4) * 16);
                }
                u32 b_[4][2];
#pragma unroll
                for (int nj2 = 0; nj2 < 2; nj2++) {
                    int row = wn * 32 + nj2 * 16 + (lane & 7) + ((lane >> 4) << 3);
                    u32 r0, r1, r2, r3;
                    ldsm4(r0, r1, r2, r3,
                          smem_u + row * W_STR + wkoff + kk * 32 + ((lane >> 3) & 1) * 16);
                    b_[nj2 * 2][0] = r0; b_[nj2 * 2][1] = r1;
                    b_[nj2 * 2 + 1][0] = r2; b_[nj2 * 2 + 1][1] = r3;
                }
#pragma unroll
                for (int nj = 0; nj < 4; nj++) {
                    mma16816(acc[nj], a[0], b_[nj]);   // h_hi * W
                    mma16816(acc[nj], a[1], b_[nj]);   // h_lo * W
                }
            }
        }
#undef ST_LOAD

        // ---- write gate tile to smem ----
#pragma unroll
        for (int nj = 0; nj < 4; nj++) {
            int n = wn * 32 + nj * 8 + (lane & 3) * 2;
            int m = wm * 16 + (lane >> 2);
            *(float2*)&gates[m * 68 + n]       = make_float2(acc[nj][0], acc[nj][1]);
            *(float2*)&gates[(m + 8) * 68 + n] = make_float2(acc[nj][2], acc[nj][3]);
        }
        __syncthreads();

        // ---- pointwise: 4 outputs/thread; write h (needed by others) first ----
        float hnv[4];
#pragma unroll
        for (int it = 0; it < 4; it++) {
            int id = it * 256 + tid;
            int b = id >> 4, jj = id & 15;
            int j = j0 + jj;
            float gi = gates[b * 68 + jj]      + presm[b * 68 + jj];
            float gf = gates[b * 68 + 16 + jj] + presm[b * 68 + 16 + jj];
            float gg = gates[b * 68 + 32 + jj] + presm[b * 68 + 32 + jj];
            float go = gates[b * 68 + 48 + jj] + presm[b * 68 + 48 + jj];
            float iv = 1.f / (1.f + expf(-gi));
            float fv = 1.f / (1.f + expf(-gf));
            float gv = tanhf(gg);
            float ov = 1.f / (1.f + expf(-go));
            float cn = fv * creg[it] + iv * gv;
            float hn = ov * tanhf(cn);
            float m = (float)mask[b * TT + t];
            float hz = h0c[it];
            hn = hn * m + hz * (1.f - m);
            cn = cn * m + hz * (1.f - m);
            creg[it] = cn;
            hnv[it] = hn;
            __half hh = __float2half_rn(hn);
            g_h_hi[dir][pp ^ 1][b * HH + j] = hh;
            g_h_lo[dir][pp ^ 1][b * HH + j] = __float2half_rn(hn - __half2float(hh));
        }

        // ---- release h, arrive on per-dir barrier ----
        __threadfence();
        __syncthreads();
        if (tid == 0) atomicAdd(&g_bar2[dir], 1u);

        // ---- deferred output writes (overlap other CTAs' arrival) ----
#pragma unroll
        for (int it = 0; it < 4; it++) {
            int id = it * 256 + tid;
            int b = id >> 4, jj = id & 15;
            int j = j0 + jj;
            // outputs stacked in ITERATION order for both directions (per reference)
            out[((size_t)s * BB + b) * (2 * HH) + (size_t)dir * HH + j] = hnv[it];
            if (s == TT - 1) {
                out[OUT_Y + (size_t)b * (2 * HH) + (size_t)dir * HH + j] = hnv[it];
                out[OUT_Y + (size_t)BB * 2 * HH + (size_t)b * (2 * HH) + (size_t)dir * HH + j] = creg[it];
            }
        }

        if (s < TT - 1) {
            if (tid == 0) {
                unsigned int target = 64u * (s + 1);
                while (ld_acq(&g_bar2[dir]) < target) { }
            }
            __syncthreads();
        }
    }
}

// ---------------- host ----------------
extern "C" void kernel_launch(void* const* d_in, const int* in_sizes, int n_in,
                              void* d_out, int out_size) {
    const float* x    = (const float*)d_in[0];
    const int*   mask = (const int*)  d_in[1];
    const float* h0   = (const float*)d_in[2];
    const float* Wihf = (const float*)d_in[3];
    const float* Whhf = (const float*)d_in[4];
    const float* bihf = (const float*)d_in[5];
    const float* bhhf = (const float*)d_in[6];
    const float* Wihb = (const float*)d_in[7];
    const float* Whhb = (const float*)d_in[8];
    const float* bihb = (const float*)d_in[9];
    const float* bhhb = (const float*)d_in[10];
    float* out = (float*)d_out;

    cudaFuncSetAttribute(precompute_mma, cudaFuncAttributeMaxDynamicSharedMemorySize, 3 * PC_STAGE);
    cudaFuncSetAttribute(step_persist,   cudaFuncAttributeMaxDynamicSharedMemorySize, ST_SMEM);

    const size_t WOFF = (size_t)G4 * HH;
    split_pair<<<8192, 256>>>(Wihf, 0, 0,    2097152);
    split_pair<<<8192, 256>>>(Wihb, 0, WOFF, 2097152);
    split_one <<<8192, 256>>>(Whhf, 0,       2097152);
    split_one <<<8192, 256>>>(Whhb, WOFF,    2097152);
    split_pair<<<32768, 256>>>(x,   1, 0,    8388608);
    init_state<<<(BB * HH) / 256, 256>>>(h0);

    precompute_mma<<<dim3(32, 256, 2), 256, 3 * PC_STAGE>>>(bihf, bhhf, bihb, bhhb);

    step_persist<<<dim3(64, 2), 256, ST_SMEM>>>(mask, h0, out);
}

// round 10
// speedup vs baseline: 2.2464x; 1.4193x over previous
#include <cuda_runtime.h>
#include <cuda_fp16.h>
#include <math.h>

#define TT 256
#define BB 64
#define HH 1024
#define G4 4096
#define OUT_Y ((size_t)TT * BB * 2 * HH)

typedef unsigned int u32;

// ---------------- scratch ----------------
__device__ float g_pre[(size_t)2 * TT * BB * G4];          // 512MB
__device__ __half g_h16[2][2][BB * HH];                    // ping-pong h (fp16)
__device__ __half g_Wih16[(size_t)2 * G4 * HH];
__device__ __half g_Whh16[(size_t)2 * G4 * HH];
__device__ __half g_x_hi[(size_t)TT * BB * HH], g_x_lo[(size_t)TT * BB * HH];
__device__ unsigned int g_bar2[2];

// ---------------- PTX helpers ----------------
__device__ __forceinline__ u32 s2u(const void* p) {
    u32 a;
    asm("{ .reg .u64 t; cvta.to.shared.u64 t, %1; cvt.u32.u64 %0, t; }" : "=r"(a) : "l"(p));
    return a;
}
__device__ __forceinline__ void cpa16(u32 d, const void* s) {
    asm volatile("cp.async.cg.shared.global [%0], [%1], 16;" :: "r"(d), "l"(s));
}
#define CP_COMMIT asm volatile("cp.async.commit_group;" ::: "memory")
#define CP_WAIT1  asm volatile("cp.async.wait_group 1;" ::: "memory")

__device__ __forceinline__ void ldsm4(u32& r0, u32& r1, u32& r2, u32& r3, u32 a) {
    asm volatile("ldmatrix.sync.aligned.m8n8.x4.shared.b16 {%0,%1,%2,%3}, [%4];"
                 : "=r"(r0), "=r"(r1), "=r"(r2), "=r"(r3) : "r"(a));
}
__device__ __forceinline__ void mma16816(float* c, const u32* a, const u32* b) {
    asm volatile(
        "mma.sync.aligned.m16n8k16.row.col.f32.f16.f16.f32 "
        "{%0,%1,%2,%3}, {%4,%5,%6,%7}, {%8,%9}, {%0,%1,%2,%3};"
        : "+f"(c[0]), "+f"(c[1]), "+f"(c[2]), "+f"(c[3])
        : "r"(a[0]), "r"(a[1]), "r"(a[2]), "r"(a[3]), "r"(b[0]), "r"(b[1]));
}
__device__ __forceinline__ u32 ld_acq(const unsigned int* p) {
    u32 v;
    asm volatile("ld.acquire.gpu.u32 %0, [%1];" : "=r"(v) : "l"(p) : "memory");
    return v;
}

// ---------------- split / init ----------------
__global__ void split_W(const float* __restrict__ src, int sel, size_t off, int n2) {
    int i = blockIdx.x * 256 + threadIdx.x;
    if (i >= n2) return;
    float2 v = ((const float2*)src)[i];
    __half* dst = (sel == 0) ? g_Wih16 : g_Whh16;
    ((__half2*)(dst + off))[i] =
        __halves2half2(__float2half_rn(v.x), __float2half_rn(v.y));
}

__global__ void split_x(const float* __restrict__ src, int n2) {
    int i = blockIdx.x * 256 + threadIdx.x;
    if (i >= n2) return;
    float2 v = ((const float2*)src)[i];
    __half h0v = __float2half_rn(v.x);
    __half h1v = __float2half_rn(v.y);
    __half l0v = __float2half_rn(v.x - __half2float(h0v));
    __half l1v = __float2half_rn(v.y - __half2float(h1v));
    ((__half2*)g_x_hi)[i] = __halves2half2(h0v, h1v);
    ((__half2*)g_x_lo)[i] = __halves2half2(l0v, l1v);
}

__global__ void init_state(const float* __restrict__ h0) {
    int i = blockIdx.x * blockDim.x + threadIdx.x;  // BB*HH threads
    if (i == 0) { g_bar2[0] = 0; g_bar2[1] = 0; }
    __half hb = __float2half_rn(h0[i]);
    g_h16[0][0][i] = hb; g_h16[1][0][i] = hb;
}

// ============================================================
// Precompute: g_pre = x @ W_ih16^T + b_ih + b_hh  (2-term: x_hi,x_lo exact)
// Block: M=64 rows (r=b*T+t), N=128 gate cols, K=1024 (32 stages of 32).
// A = [x_hi(64); x_lo(64)] stacked, both accumulate into same output rows.
// ============================================================
#define PC_STAGE 20480
__global__ __launch_bounds__(256, 2) void precompute_mma(
    const float* __restrict__ bihf, const float* __restrict__ bhhf,
    const float* __restrict__ bihb, const float* __restrict__ bhhb)
{
    extern __shared__ char smem[];
    const u32 smem_u = s2u(smem);
    const int tid = threadIdx.x, lane = tid & 31, wid = tid >> 5;
    const int wm = wid >> 2, wn = wid & 3;
    const int c0 = blockIdx.x * 128, rb = blockIdx.y, dir = blockIdx.z;

    const __half* __restrict__ Ah = g_x_hi + (size_t)rb * 64 * HH;
    const __half* __restrict__ Al = g_x_lo + (size_t)rb * 64 * HH;
    const __half* __restrict__ Bw = g_Wih16 + ((size_t)dir * G4 + c0) * HH;

    float acc[2][4][4];
#pragma unroll
    for (int mi = 0; mi < 2; mi++)
#pragma unroll
        for (int nj = 0; nj < 4; nj++)
#pragma unroll
            for (int q = 0; q < 4; q++) acc[mi][nj][q] = 0.f;

#define PC_LOAD(st, buf) do { \
    int ko_ = (st) * 32; \
    u32 ab_ = smem_u + (buf) * PC_STAGE; \
    _Pragma("unroll") \
    for (int it = 0; it < 2; it++) { \
        int id = it * 256 + tid, row = id >> 2, c = id & 3; \
        const __half* s_ = (row < 64 ? Ah + (size_t)row * HH \
                                     : Al + (size_t)(row - 64) * HH) + ko_ + c * 8; \
        cpa16(ab_ + row * 80 + c * 16, s_); \
    } \
    u32 bb_ = ab_ + 10240; \
    _Pragma("unroll") \
    for (int it = 0; it < 2; it++) { \
        int id = it * 256 + tid, row = id >> 2, c = id & 3; \
        cpa16(bb_ + row * 80 + c * 16, Bw + (size_t)row * HH + ko_ + c * 8); \
    } \
} while (0)

    PC_LOAD(0, 0); CP_COMMIT;
    PC_LOAD(1, 1); CP_COMMIT;
    for (int st = 0; st < 32; st++) {
        CP_WAIT1;
        __syncthreads();
        if (st + 2 < 32) { int bf = (st + 2) % 3; PC_LOAD(st + 2, bf); }
        CP_COMMIT;
        const u32 abase = smem_u + (st % 3) * PC_STAGE;
        const u32 bbase = abase + 10240;
#pragma unroll
        for (int kk = 0; kk < 2; kk++) {
            u32 a[2][2][4];
#pragma unroll
            for (int hl = 0; hl < 2; hl++)
#pragma unroll
                for (int mi = 0; mi < 2; mi++) {
                    int row = hl * 64 + wm * 32 + mi * 16 + (lane & 15);
                    ldsm4(a[hl][mi][0], a[hl][mi][1], a[hl][mi][2], a[hl][mi][3],
                          abase + row * 80 + kk * 32 + (lane >> 4) * 16);
                }
            u32 b_[4][2];
#pragma unroll
            for (int nj2 = 0; nj2 < 2; nj2++) {
                int row = wn * 32 + nj2 * 16 + (lane & 7) + ((lane >> 4) << 3);
                u32 r0, r1, r2, r3;
                ldsm4(r0, r1, r2, r3,
                      bbase + row * 80 + kk * 32 + ((lane >> 3) & 1) * 16);
                b_[nj2 * 2][0] = r0; b_[nj2 * 2][1] = r1;
                b_[nj2 * 2 + 1][0] = r2; b_[nj2 * 2 + 1][1] = r3;
            }
#pragma unroll
            for (int mi = 0; mi < 2; mi++)
#pragma unroll
                for (int nj = 0; nj < 4; nj++) {
                    mma16816(acc[mi][nj], a[0][mi], b_[nj]);  // x_hi * W
                    mma16816(acc[mi][nj], a[1][mi], b_[nj]);  // x_lo * W
                }
        }
    }
#undef PC_LOAD

    const float* bi = dir ? bihb : bihf;
    const float* bh = dir ? bhhb : bhhf;
#pragma unroll
    for (int nj = 0; nj < 4; nj++) {
        int n = c0 + wn * 32 + nj * 8 + (lane & 3) * 2;
        float bz0 = bi[n] + bh[n];
        float bz1 = bi[n + 1] + bh[n + 1];
#pragma unroll
        for (int mi = 0; mi < 2; mi++)
#pragma unroll
            for (int hrow = 0; hrow < 2; hrow++) {
                int m = wm * 32 + mi * 16 + (lane >> 2) + hrow * 8;
                int r = rb * 64 + m, t = r & (TT - 1), bb2 = r >> 8;
                float* dst = g_pre + (((size_t)dir * TT + t) * BB + bb2) * G4 + n;
                float2 o;
                o.x = acc[mi][nj][hrow * 2 + 0] + bz0;
                o.y = acc[mi][nj][hrow * 2 + 1] + bz1;
                *(float2*)dst = o;
            }
    }
}

// ============================================================
// Persistent fused LSTM. 128 CTAs (64 j-tiles x 2 dirs), 1/SM.
// W_hh slice (64 gate-cols x 1024 k fp16) RESIDENT in smem.
// Per step: stream h16 (1-term GEMM, M=64 N=64 K=1024, 16 stages of 64k)
// -> gates -> pointwise. c in registers. Per-dir spin barrier.
// smem: W 132096 | A 3x9216 | gates 64x68 f32 | pre 64x68 f32
// ============================================================
#define W_STR 2064
#define A_OFF 132096
#define A_STAGE 9216
#define GATES_OFF 159744
#define PRE_OFF 177152
#define ST_SMEM 194560

__global__ __launch_bounds__(256, 1) void step_persist(
    const int* __restrict__ mask, const float* __restrict__ h0,
    float* __restrict__ out)
{
    extern __shared__ char smem[];
    const u32 smem_u = s2u(smem);
    const int tid = threadIdx.x, lane = tid & 31, wid = tid >> 5;
    const int wm = wid >> 1, wn = wid & 1;
    const int j0 = blockIdx.x * 16, dir = blockIdx.y;

    // ---- load resident W (64 gate-cols x 1024 k fp16) ----
    {
        const __half* W = g_Whh16 + (size_t)dir * G4 * HH;
#pragma unroll
        for (int it = 0; it < 32; it++) {
            int id = it * 256 + tid;
            int row = id >> 7, c = id & 127;       // row: gate-col, c: 16B chunk
            int grp = row >> 4, jj = row & 15;
            cpa16(smem_u + row * W_STR + c * 16,
                  W + (size_t)(grp * HH + j0 + jj) * HH + c * 8);
        }
        CP_COMMIT;
    }

    // ---- per-thread persistent state: h0 cache + c registers ----
    float h0c[4], creg[4];
#pragma unroll
    for (int it = 0; it < 4; it++) {
        int id = it * 256 + tid;
        int b = id >> 4, jj = id & 15;
        h0c[it] = h0[b * HH + j0 + jj];
        creg[it] = h0c[it];
    }

    float* gates = (float*)(smem + GATES_OFF);
    const float* presm = (const float*)(smem + PRE_OFF);

    for (int s = 0; s < TT; s++) {
        const int pp = s & 1;
        const int t = dir ? (TT - 1 - s) : s;
        const __half* __restrict__ Ah = g_h16[dir][pp];
        const float* __restrict__ preg = g_pre + ((size_t)dir * TT + t) * BB * G4;

        float acc[4][4];
#pragma unroll
        for (int nj = 0; nj < 4; nj++)
#pragma unroll
            for (int q = 0; q < 4; q++) acc[nj][q] = 0.f;

#define ST_LOAD(st, buf) do { \
    int ko_ = (st) * 64; \
    u32 ab_ = smem_u + A_OFF + (buf) * A_STAGE; \
    _Pragma("unroll") \
    for (int it = 0; it < 2; it++) { \
        int id = it * 256 + tid, row = id >> 3, c = id & 7; \
        cpa16(ab_ + row * 144 + c * 16, Ah + (size_t)row * HH + ko_ + c * 8); \
    } \
} while (0)

        // stage 0 + pre-gate tile prefetch in one group
        ST_LOAD(0, 0);
#pragma unroll
        for (int it = 0; it < 4; it++) {
            int id = it * 256 + tid;
            int b = id >> 4, seg = (id >> 2) & 3, q = id & 3;
            cpa16(smem_u + PRE_OFF + b * 272 + seg * 64 + q * 16,
                  preg + (size_t)b * G4 + seg * HH + j0 + q * 4);
        }
        CP_COMMIT;
        ST_LOAD(1, 1); CP_COMMIT;

        for (int st = 0; st < 16; st++) {
            CP_WAIT1;
            __syncthreads();
            if (st + 2 < 16) { int bf = (st + 2) % 3; ST_LOAD(st + 2, bf); }
            CP_COMMIT;
            const u32 abase = smem_u + A_OFF + (st % 3) * A_STAGE;
            const u32 wkoff = st * 128;
#pragma unroll
            for (int kk = 0; kk < 4; kk++) {
                u32 a[4];
                {
                    int row = wm * 16 + (lane & 15);
                    ldsm4(a[0], a[1], a[2], a[3],
                          abase + row * 144 + kk * 32 + (lane >> 4) * 16);
                }
                u32 b_[4][2];
#pragma unroll
                for (int nj2 = 0; nj2 < 2; nj2++) {
                    int row = wn * 32 + nj2 * 16 + (lane & 7) + ((lane >> 4) << 3);
                    u32 r0, r1, r2, r3;
                    ldsm4(r0, r1, r2, r3,
                          smem_u + row * W_STR + wkoff + kk * 32 + ((lane >> 3) & 1) * 16);
                    b_[nj2 * 2][0] = r0; b_[nj2 * 2][1] = r1;
                    b_[nj2 * 2 + 1][0] = r2; b_[nj2 * 2 + 1][1] = r3;
                }
#pragma unroll
                for (int nj = 0; nj < 4; nj++)
                    mma16816(acc[nj], a, b_[nj]);   // h16 * W16
            }
        }
#undef ST_LOAD

        // ---- write gate tile to smem ----
#pragma unroll
        for (int nj = 0; nj < 4; nj++) {
            int n = wn * 32 + nj * 8 + (lane & 3) * 2;
            int m = wm * 16 + (lane >> 2);
            *(float2*)&gates[m * 68 + n]       = make_float2(acc[nj][0], acc[nj][1]);
            *(float2*)&gates[(m + 8) * 68 + n] = make_float2(acc[nj][2], acc[nj][3]);
        }
        __syncthreads();

        // ---- pointwise: 4 outputs/thread; write h (needed by others) first ----
        float hnv[4];
#pragma unroll
        for (int it = 0; it < 4; it++) {
            int id = it * 256 + tid;
            int b = id >> 4, jj = id & 15;
            int j = j0 + jj;
            float gi = gates[b * 68 + jj]      + presm[b * 68 + jj];
            float gf = gates[b * 68 + 16 + jj] + presm[b * 68 + 16 + jj];
            float gg = gates[b * 68 + 32 + jj] + presm[b * 68 + 32 + jj];
            float go = gates[b * 68 + 48 + jj] + presm[b * 68 + 48 + jj];
            float iv = 1.f / (1.f + expf(-gi));
            float fv = 1.f / (1.f + expf(-gf));
            float gv = tanhf(gg);
            float ov = 1.f / (1.f + expf(-go));
            float cn = fv * creg[it] + iv * gv;
            float hn = ov * tanhf(cn);
            float m = (float)mask[b * TT + t];
            float hz = h0c[it];
            hn = hn * m + hz * (1.f - m);
            cn = cn * m + hz * (1.f - m);
            creg[it] = cn;
            hnv[it] = hn;
            g_h16[dir][pp ^ 1][b * HH + j] = __float2half_rn(hn);
        }

        // ---- release h, arrive on per-dir barrier ----
        __threadfence();
        __syncthreads();
        if (tid == 0) atomicAdd(&g_bar2[dir], 1u);

        // ---- deferred output writes (overlap other CTAs' arrival) ----
#pragma unroll
        for (int it = 0; it < 4; it++) {
            int id = it * 256 + tid;
            int b = id >> 4, jj = id & 15;
            int j = j0 + jj;
            // outputs stacked in ITERATION order for both directions (per reference)
            out[((size_t)s * BB + b) * (2 * HH) + (size_t)dir * HH + j] = hnv[it];
            if (s == TT - 1) {
                out[OUT_Y + (size_t)b * (2 * HH) + (size_t)dir * HH + j] = hnv[it];
                out[OUT_Y + (size_t)BB * 2 * HH + (size_t)b * (2 * HH) + (size_t)dir * HH + j] = creg[it];
            }
        }

        if (s < TT - 1) {
            if (tid == 0) {
                unsigned int target = 64u * (s + 1);
                while (ld_acq(&g_bar2[dir]) < target) { }
            }
            __syncthreads();
        }
    }
}

// ---------------- host ----------------
extern "C" void kernel_launch(void* const* d_in, const int* in_sizes, int n_in,
                              void* d_out, int out_size) {
    const float* x    = (const float*)d_in[0];
    const int*   mask = (const int*)  d_in[1];
    const float* h0   = (const float*)d_in[2];
    const float* Wihf = (const float*)d_in[3];
    const float* Whhf = (const float*)d_in[4];
    const float* bihf = (const float*)d_in[5];
    const float* bhhf = (const float*)d_in[6];
    const float* Wihb = (const float*)d_in[7];
    const float* Whhb = (const float*)d_in[8];
    const float* bihb = (const float*)d_in[9];
    const float* bhhb = (const float*)d_in[10];
    float* out = (float*)d_out;

    cudaFuncSetAttribute(precompute_mma, cudaFuncAttributeMaxDynamicSharedMemorySize, 3 * PC_STAGE);
    cudaFuncSetAttribute(step_persist,   cudaFuncAttributeMaxDynamicSharedMemorySize, ST_SMEM);

    const size_t WOFF = (size_t)G4 * HH;
    split_W<<<8192, 256>>>(Wihf, 0, 0,    2097152);
    split_W<<<8192, 256>>>(Wihb, 0, WOFF, 2097152);
    split_W<<<8192, 256>>>(Whhf, 1, 0,    2097152);
    split_W<<<8192, 256>>>(Whhb, 1, WOFF, 2097152);
    split_x<<<32768, 256>>>(x, 8388608);
    init_state<<<(BB * HH) / 256, 256>>>(h0);

    precompute_mma<<<dim3(32, 256, 2), 256, 3 * PC_STAGE>>>(bihf, bhhf, bihb, bhhb);

    step_persist<<<dim3(64, 2), 256, ST_SMEM>>>(mask, h0, out);
}

// round 11
// speedup vs baseline: 2.8898x; 1.2864x over previous
#include <cuda_runtime.h>
#include <cuda_fp16.h>
#include <math.h>

#define TT 256
#define BB 64
#define HH 1024
#define G4 4096
#define OUT_Y ((size_t)TT * BB * 2 * HH)

typedef unsigned int u32;

// ---------------- scratch ----------------
__device__ float g_pre[(size_t)2 * TT * BB * G4];          // 512MB
__device__ __half g_h16[2][2][BB * HH];                    // ping-pong h (fp16)
__device__ __half g_Wih16[(size_t)2 * G4 * HH];
__device__ __half g_Whh16[(size_t)2 * G4 * HH];
__device__ __half g_x16[(size_t)TT * BB * HH];
__device__ unsigned int g_bar2[2];

// ---------------- PTX helpers ----------------
__device__ __forceinline__ u32 s2u(const void* p) {
    u32 a;
    asm("{ .reg .u64 t; cvta.to.shared.u64 t, %1; cvt.u32.u64 %0, t; }" : "=r"(a) : "l"(p));
    return a;
}
__device__ __forceinline__ void cpa16(u32 d, const void* s) {
    asm volatile("cp.async.cg.shared.global [%0], [%1], 16;" :: "r"(d), "l"(s));
}
#define CP_COMMIT asm volatile("cp.async.commit_group;" ::: "memory")
#define CP_WAIT1  asm volatile("cp.async.wait_group 1;" ::: "memory")

__device__ __forceinline__ void ldsm4(u32& r0, u32& r1, u32& r2, u32& r3, u32 a) {
    asm volatile("ldmatrix.sync.aligned.m8n8.x4.shared.b16 {%0,%1,%2,%3}, [%4];"
                 : "=r"(r0), "=r"(r1), "=r"(r2), "=r"(r3) : "r"(a));
}
__device__ __forceinline__ void mma16816(float* c, const u32* a, const u32* b) {
    asm volatile(
        "mma.sync.aligned.m16n8k16.row.col.f32.f16.f16.f32 "
        "{%0,%1,%2,%3}, {%4,%5,%6,%7}, {%8,%9}, {%0,%1,%2,%3};"
        : "+f"(c[0]), "+f"(c[1]), "+f"(c[2]), "+f"(c[3])
        : "r"(a[0]), "r"(a[1]), "r"(a[2]), "r"(a[3]), "r"(b[0]), "r"(b[1]));
}
__device__ __forceinline__ u32 ld_acq(const unsigned int* p) {
    u32 v;
    asm volatile("ld.acquire.gpu.u32 %0, [%1];" : "=r"(v) : "l"(p) : "memory");
    return v;
}
// fast sigmoid/tanh via MUFU (err ~1e-6, independent of harness math flags)
__device__ __forceinline__ float fsig(float x) {
    float t, r;
    asm("ex2.approx.ftz.f32 %0, %1;" : "=f"(t) : "f"(-x * 1.442695041f));
    asm("rcp.approx.ftz.f32 %0, %1;" : "=f"(r) : "f"(1.f + t));
    return r;
}
__device__ __forceinline__ float ftanh(float x) {
    float t, r;
    asm("ex2.approx.ftz.f32 %0, %1;" : "=f"(t) : "f"(x * 2.885390082f));  // e^{2x}
    asm("rcp.approx.ftz.f32 %0, %1;" : "=f"(r) : "f"(1.f + t));
    return 1.f - 2.f * r;
}

// ---------------- convert / init ----------------
__global__ void to_fp16(const float* __restrict__ src, int sel, size_t off, int n2) {
    int i = blockIdx.x * 256 + threadIdx.x;
    if (i >= n2) return;
    float2 v = ((const float2*)src)[i];
    __half* dst = (sel == 0) ? g_Wih16 : (sel == 1) ? g_Whh16 : g_x16;
    ((__half2*)(dst + off))[i] =
        __halves2half2(__float2half_rn(v.x), __float2half_rn(v.y));
}

__global__ void init_state(const float* __restrict__ h0) {
    int i = blockIdx.x * blockDim.x + threadIdx.x;  // BB*HH threads
    if (i == 0) { g_bar2[0] = 0; g_bar2[1] = 0; }
    __half hb = __float2half_rn(h0[i]);
    g_h16[0][0][i] = hb; g_h16[1][0][i] = hb;
}

// ============================================================
// Precompute: g_pre = x16 @ W_ih16^T + b_ih + b_hh  (1-term fp16)
// Block: M=64 rows (r=b*T+t), N=128 gate cols, K=1024 (32 stages of 32).
// ============================================================
#define PC_STAGE 15360
__global__ __launch_bounds__(256, 2) void precompute_mma(
    const float* __restrict__ bihf, const float* __restrict__ bhhf,
    const float* __restrict__ bihb, const float* __restrict__ bhhb)
{
    extern __shared__ char smem[];
    const u32 smem_u = s2u(smem);
    const int tid = threadIdx.x, lane = tid & 31, wid = tid >> 5;
    const int wm = wid >> 2, wn = wid & 3;
    const int c0 = blockIdx.x * 128, rb = blockIdx.y, dir = blockIdx.z;

    const __half* __restrict__ Ax = g_x16 + (size_t)rb * 64 * HH;
    const __half* __restrict__ Bw = g_Wih16 + ((size_t)dir * G4 + c0) * HH;

    float acc[2][4][4];
#pragma unroll
    for (int mi = 0; mi < 2; mi++)
#pragma unroll
        for (int nj = 0; nj < 4; nj++)
#pragma unroll
            for (int q = 0; q < 4; q++) acc[mi][nj][q] = 0.f;

#define PC_LOAD(st, buf) do { \
    int ko_ = (st) * 32; \
    u32 ab_ = smem_u + (buf) * PC_STAGE; \
    { \
        int row = tid >> 2, c = tid & 3; \
        cpa16(ab_ + row * 80 + c * 16, Ax + (size_t)row * HH + ko_ + c * 8); \
    } \
    u32 bb_ = ab_ + 5120; \
    _Pragma("unroll") \
    for (int it = 0; it < 2; it++) { \
        int id = it * 256 + tid, row = id >> 2, c = id & 3; \
        cpa16(bb_ + row * 80 + c * 16, Bw + (size_t)row * HH + ko_ + c * 8); \
    } \
} while (0)

    PC_LOAD(0, 0); CP_COMMIT;
    PC_LOAD(1, 1); CP_COMMIT;
    for (int st = 0; st < 32; st++) {
        CP_WAIT1;
        __syncthreads();
        if (st + 2 < 32) { int bf = (st + 2) % 3; PC_LOAD(st + 2, bf); }
        CP_COMMIT;
        const u32 abase = smem_u + (st % 3) * PC_STAGE;
        const u32 bbase = abase + 5120;
#pragma unroll
        for (int kk = 0; kk < 2; kk++) {
            u32 a[2][4];
#pragma unroll
            for (int mi = 0; mi < 2; mi++) {
                int row = wm * 32 + mi * 16 + (lane & 15);
                ldsm4(a[mi][0], a[mi][1], a[mi][2], a[mi][3],
                      abase + row * 80 + kk * 32 + (lane >> 4) * 16);
            }
            u32 b_[4][2];
#pragma unroll
            for (int nj2 = 0; nj2 < 2; nj2++) {
                int row = wn * 32 + nj2 * 16 + (lane & 7) + ((lane >> 4) << 3);
                u32 r0, r1, r2, r3;
                ldsm4(r0, r1, r2, r3,
                      bbase + row * 80 + kk * 32 + ((lane >> 3) & 1) * 16);
                b_[nj2 * 2][0] = r0; b_[nj2 * 2][1] = r1;
                b_[nj2 * 2 + 1][0] = r2; b_[nj2 * 2 + 1][1] = r3;
            }
#pragma unroll
            for (int mi = 0; mi < 2; mi++)
#pragma unroll
                for (int nj = 0; nj < 4; nj++)
                    mma16816(acc[mi][nj], a[mi], b_[nj]);
        }
    }
#undef PC_LOAD

    const float* bi = dir ? bihb : bihf;
    const float* bh = dir ? bhhb : bhhf;
#pragma unroll
    for (int nj = 0; nj < 4; nj++) {
        int n = c0 + wn * 32 + nj * 8 + (lane & 3) * 2;
        float bz0 = bi[n] + bh[n];
        float bz1 = bi[n + 1] + bh[n + 1];
#pragma unroll
        for (int mi = 0; mi < 2; mi++)
#pragma unroll
            for (int hrow = 0; hrow < 2; hrow++) {
                int m = wm * 32 + mi * 16 + (lane >> 2) + hrow * 8;
                int r = rb * 64 + m, t = r & (TT - 1), bb2 = r >> 8;
                float* dst = g_pre + (((size_t)dir * TT + t) * BB + bb2) * G4 + n;
                float2 o;
                o.x = acc[mi][nj][hrow * 2 + 0] + bz0;
                o.y = acc[mi][nj][hrow * 2 + 1] + bz1;
                *(float2*)dst = o;
            }
    }
}

// ============================================================
// Persistent fused LSTM. 128 CTAs (64 j-tiles x 2 dirs), 1/SM.
// W_hh slice (64 gate-cols x 1024 k fp16) RESIDENT in smem.
// Per step: stream h16 (M=64 N=64 K=1024, 8 stages of 128k) ->
// gates -> pointwise (MUFU fast math). c in regs. Per-dir spin barrier.
// smem: W 132096 | A 3x17408 | gates 64x68 f32 | pre 64x68 f32
// ============================================================
#define W_STR 2064
#define A_OFF 132096
#define A_STAGE 17408
#define GATES_OFF 184320
#define PRE_OFF 201728
#define ST_SMEM 219136

__global__ __launch_bounds__(256, 1) void step_persist(
    const int* __restrict__ mask, const float* __restrict__ h0,
    float* __restrict__ out)
{
    extern __shared__ char smem[];
    const u32 smem_u = s2u(smem);
    const int tid = threadIdx.x, lane = tid & 31, wid = tid >> 5;
    const int wm = wid >> 1, wn = wid & 1;
    const int j0 = blockIdx.x * 16, dir = blockIdx.y;

    // ---- load resident W (64 gate-cols x 1024 k fp16) ----
    {
        const __half* W = g_Whh16 + (size_t)dir * G4 * HH;
#pragma unroll
        for (int it = 0; it < 32; it++) {
            int id = it * 256 + tid;
            int row = id >> 7, c = id & 127;       // row: gate-col, c: 16B chunk
            int grp = row >> 4, jj = row & 15;
            cpa16(smem_u + row * W_STR + c * 16,
                  W + (size_t)(grp * HH + j0 + jj) * HH + c * 8);
        }
        CP_COMMIT;
    }

    // ---- per-thread persistent state ----
    float h0c[4], creg[4];
#pragma unroll
    for (int it = 0; it < 4; it++) {
        int id = it * 256 + tid;
        int b = id >> 4, jj = id & 15;
        h0c[it] = h0[b * HH + j0 + jj];
        creg[it] = h0c[it];
    }

    float* gates = (float*)(smem + GATES_OFF);
    const float* presm = (const float*)(smem + PRE_OFF);

    for (int s = 0; s < TT; s++) {
        const int pp = s & 1;
        const int t = dir ? (TT - 1 - s) : s;
        const __half* __restrict__ Ah = g_h16[dir][pp];
        const float* __restrict__ preg = g_pre + ((size_t)dir * TT + t) * BB * G4;

        float acc[4][4];
#pragma unroll
        for (int nj = 0; nj < 4; nj++)
#pragma unroll
            for (int q = 0; q < 4; q++) acc[nj][q] = 0.f;

#define ST_LOAD(st, buf) do { \
    int ko_ = (st) * 128; \
    u32 ab_ = smem_u + A_OFF + (buf) * A_STAGE; \
    _Pragma("unroll") \
    for (int it = 0; it < 4; it++) { \
        int id = it * 256 + tid, row = id >> 4, c = id & 15; \
        cpa16(ab_ + row * 272 + c * 16, Ah + (size_t)row * HH + ko_ + c * 8); \
    } \
} while (0)

        // stage 0 + pre-gate tile prefetch in one group
        ST_LOAD(0, 0);
#pragma unroll
        for (int it = 0; it < 4; it++) {
            int id = it * 256 + tid;
            int b = id >> 4, seg = (id >> 2) & 3, q = id & 3;
            cpa16(smem_u + PRE_OFF + b * 272 + seg * 64 + q * 16,
                  preg + (size_t)b * G4 + seg * HH + j0 + q * 4);
        }
        CP_COMMIT;
        ST_LOAD(1, 1); CP_COMMIT;

        // mask prefetch into regs (issues early, consumed at pointwise)
        float mreg[4];
#pragma unroll
        for (int it = 0; it < 4; it++) {
            int id = it * 256 + tid, b = id >> 4;
            mreg[it] = (float)__ldg(&mask[b * TT + t]);
        }

        for (int st = 0; st < 8; st++) {
            CP_WAIT1;
            __syncthreads();
            if (st + 2 < 8) { int bf = (st + 2) % 3; ST_LOAD(st + 2, bf); }
            CP_COMMIT;
            const u32 abase = smem_u + A_OFF + (st % 3) * A_STAGE;
            const u32 wkoff = st * 256;
#pragma unroll
            for (int kk = 0; kk < 8; kk++) {
                u32 a[4];
                {
                    int row = wm * 16 + (lane & 15);
                    ldsm4(a[0], a[1], a[2], a[3],
                          abase + row * 272 + kk * 32 + (lane >> 4) * 16);
                }
                u32 b_[4][2];
#pragma unroll
                for (int nj2 = 0; nj2 < 2; nj2++) {
                    int row = wn * 32 + nj2 * 16 + (lane & 7) + ((lane >> 4) << 3);
                    u32 r0, r1, r2, r3;
                    ldsm4(r0, r1, r2, r3,
                          smem_u + row * W_STR + wkoff + kk * 32 + ((lane >> 3) & 1) * 16);
                    b_[nj2 * 2][0] = r0; b_[nj2 * 2][1] = r1;
                    b_[nj2 * 2 + 1][0] = r2; b_[nj2 * 2 + 1][1] = r3;
                }
#pragma unroll
                for (int nj = 0; nj < 4; nj++)
                    mma16816(acc[nj], a, b_[nj]);   // h16 * W16
            }
        }
#undef ST_LOAD

        // ---- write gate tile to smem ----
#pragma unroll
        for (int nj = 0; nj < 4; nj++) {
            int n = wn * 32 + nj * 8 + (lane & 3) * 2;
            int m = wm * 16 + (lane >> 2);
            *(float2*)&gates[m * 68 + n]       = make_float2(acc[nj][0], acc[nj][1]);
            *(float2*)&gates[(m + 8) * 68 + n] = make_float2(acc[nj][2], acc[nj][3]);
        }
        __syncthreads();

        // ---- pointwise: 4 outputs/thread; write h (needed by others) first ----
        float hnv[4];
#pragma unroll
        for (int it = 0; it < 4; it++) {
            int id = it * 256 + tid;
            int b = id >> 4, jj = id & 15;
            int j = j0 + jj;
            float gi = gates[b * 68 + jj]      + presm[b * 68 + jj];
            float gf = gates[b * 68 + 16 + jj] + presm[b * 68 + 16 + jj];
            float gg = gates[b * 68 + 32 + jj] + presm[b * 68 + 32 + jj];
            float go = gates[b * 68 + 48 + jj] + presm[b * 68 + 48 + jj];
            float iv = fsig(gi);
            float fv = fsig(gf);
            float gv = ftanh(gg);
            float ov = fsig(go);
            float cn = fv * creg[it] + iv * gv;
            float hn = ov * ftanh(cn);
            float m = mreg[it];
            float hz = h0c[it];
            hn = hn * m + hz * (1.f - m);
            cn = cn * m + hz * (1.f - m);
            creg[it] = cn;
            hnv[it] = hn;
            g_h16[dir][pp ^ 1][b * HH + j] = __float2half_rn(hn);
        }

        // ---- release h, arrive on per-dir barrier ----
        __threadfence();
        __syncthreads();
        if (tid == 0) atomicAdd(&g_bar2[dir], 1u);

        // ---- deferred output writes (overlap other CTAs' arrival) ----
#pragma unroll
        for (int it = 0; it < 4; it++) {
            int id = it * 256 + tid;
            int b = id >> 4, jj = id & 15;
            int j = j0 + jj;
            // outputs stacked in ITERATION order for both directions (per reference)
            out[((size_t)s * BB + b) * (2 * HH) + (size_t)dir * HH + j] = hnv[it];
            if (s == TT - 1) {
                out[OUT_Y + (size_t)b * (2 * HH) + (size_t)dir * HH + j] = hnv[it];
                out[OUT_Y + (size_t)BB * 2 * HH + (size_t)b * (2 * HH) + (size_t)dir * HH + j] = creg[it];
            }
        }

        if (s < TT - 1) {
            if (tid == 0) {
                unsigned int target = 64u * (s + 1);
                while (ld_acq(&g_bar2[dir]) < target) { }
            }
            __syncthreads();
        }
    }
}

// ---------------- host ----------------
extern "C" void kernel_launch(void* const* d_in, const int* in_sizes, int n_in,
                              void* d_out, int out_size) {
    const float* x    = (const float*)d_in[0];
    const int*   mask = (const int*)  d_in[1];
    const float* h0   = (const float*)d_in[2];
    const float* Wihf = (const float*)d_in[3];
    const float* Whhf = (const float*)d_in[4];
    const float* bihf = (const float*)d_in[5];
    const float* bhhf = (const float*)d_in[6];
    const float* Wihb = (const float*)d_in[7];
    const float* Whhb = (const float*)d_in[8];
    const float* bihb = (const float*)d_in[9];
    const float* bhhb = (const float*)d_in[10];
    float* out = (float*)d_out;

    cudaFuncSetAttribute(precompute_mma, cudaFuncAttributeMaxDynamicSharedMemorySize, 3 * PC_STAGE);
    cudaFuncSetAttribute(step_persist,   cudaFuncAttributeMaxDynamicSharedMemorySize, ST_SMEM);

    const size_t WOFF = (size_t)G4 * HH;
    to_fp16<<<8192, 256>>>(Wihf, 0, 0,    2097152);
    to_fp16<<<8192, 256>>>(Wihb, 0, WOFF, 2097152);
    to_fp16<<<8192, 256>>>(Whhf, 1, 0,    2097152);
    to_fp16<<<8192, 256>>>(Whhb, 1, WOFF, 2097152);
    to_fp16<<<32768, 256>>>(x,   2, 0,    8388608);
    init_state<<<(BB * HH) / 256, 256>>>(h0);

    precompute_mma<<<dim3(32, 256, 2), 256, 3 * PC_STAGE>>>(bihf, bhhf, bihb, bhhb);

    step_persist<<<dim3(64, 2), 256, ST_SMEM>>>(mask, h0, out);
}

// round 12
// speedup vs baseline: 3.2510x; 1.1250x over previous
#include <cuda_runtime.h>
#include <cuda_fp16.h>
#include <math.h>

#define TT 256
#define BB 64
#define HH 1024
#define G4 4096
#define OUT_Y ((size_t)TT * BB * 2 * HH)

typedef unsigned int u32;

// ---------------- scratch ----------------
__device__ __half g_pre16[(size_t)2 * TT * BB * G4];       // 256MB
__device__ __half g_h16[2][2][BB * HH];                    // ping-pong h (fp16)
__device__ __half g_Wih16[(size_t)2 * G4 * HH];
__device__ __half g_Whh16[(size_t)2 * G4 * HH];
__device__ __half g_x16[(size_t)TT * BB * HH];
__device__ unsigned int g_bar2[2];

// ---------------- PTX helpers ----------------
__device__ __forceinline__ u32 s2u(const void* p) {
    u32 a;
    asm("{ .reg .u64 t; cvta.to.shared.u64 t, %1; cvt.u32.u64 %0, t; }" : "=r"(a) : "l"(p));
    return a;
}
__device__ __forceinline__ void cpa16(u32 d, const void* s) {
    asm volatile("cp.async.cg.shared.global [%0], [%1], 16;" :: "r"(d), "l"(s));
}
#define CP_COMMIT asm volatile("cp.async.commit_group;" ::: "memory")
#define CP_WAIT1  asm volatile("cp.async.wait_group 1;" ::: "memory")

__device__ __forceinline__ void ldsm4(u32& r0, u32& r1, u32& r2, u32& r3, u32 a) {
    asm volatile("ldmatrix.sync.aligned.m8n8.x4.shared.b16 {%0,%1,%2,%3}, [%4];"
                 : "=r"(r0), "=r"(r1), "=r"(r2), "=r"(r3) : "r"(a));
}
__device__ __forceinline__ void mma16816(float* c, const u32* a, const u32* b) {
    asm volatile(
        "mma.sync.aligned.m16n8k16.row.col.f32.f16.f16.f32 "
        "{%0,%1,%2,%3}, {%4,%5,%6,%7}, {%8,%9}, {%0,%1,%2,%3};"
        : "+f"(c[0]), "+f"(c[1]), "+f"(c[2]), "+f"(c[3])
        : "r"(a[0]), "r"(a[1]), "r"(a[2]), "r"(a[3]), "r"(b[0]), "r"(b[1]));
}
__device__ __forceinline__ u32 ld_acq(const unsigned int* p) {
    u32 v;
    asm volatile("ld.acquire.gpu.u32 %0, [%1];" : "=r"(v) : "l"(p) : "memory");
    return v;
}
__device__ __forceinline__ void red_release_add(unsigned int* p, u32 v) {
    asm volatile("red.release.gpu.global.add.u32 [%0], %1;" :: "l"(p), "r"(v) : "memory");
}
// fast sigmoid/tanh via MUFU (err ~1e-6, independent of harness math flags)
__device__ __forceinline__ float fsig(float x) {
    float t, r;
    asm("ex2.approx.ftz.f32 %0, %1;" : "=f"(t) : "f"(-x * 1.442695041f));
    asm("rcp.approx.ftz.f32 %0, %1;" : "=f"(r) : "f"(1.f + t));
    return r;
}
__device__ __forceinline__ float ftanh(float x) {
    float t, r;
    asm("ex2.approx.ftz.f32 %0, %1;" : "=f"(t) : "f"(x * 2.885390082f));  // e^{2x}
    asm("rcp.approx.ftz.f32 %0, %1;" : "=f"(r) : "f"(1.f + t));
    return 1.f - 2.f * r;
}

// ---------------- convert / init ----------------
__global__ void to_fp16(const float* __restrict__ src, int sel, size_t off, int n2) {
    int i = blockIdx.x * 256 + threadIdx.x;
    if (i >= n2) return;
    float2 v = ((const float2*)src)[i];
    __half* dst = (sel == 0) ? g_Wih16 : (sel == 1) ? g_Whh16 : g_x16;
    ((__half2*)(dst + off))[i] =
        __halves2half2(__float2half_rn(v.x), __float2half_rn(v.y));
}

__global__ void init_state(const float* __restrict__ h0) {
    int i = blockIdx.x * blockDim.x + threadIdx.x;  // BB*HH threads
    if (i == 0) { g_bar2[0] = 0; g_bar2[1] = 0; }
    __half hb = __float2half_rn(h0[i]);
    g_h16[0][0][i] = hb; g_h16[1][0][i] = hb;
}

// ============================================================
// Precompute: g_pre16 = fp16(x16 @ W_ih16^T + b_ih + b_hh)
// Block: M=128 rows (r=b*T+t), N=128 gate cols, K=1024 (32 stages of 32).
// 8 warps: wm=wid>>2 (M64), wn=wid&3 (N32). Warp tile 64x32.
// ============================================================
#define PC_STAGE 20480
__global__ __launch_bounds__(256, 2) void precompute_mma(
    const float* __restrict__ bihf, const float* __restrict__ bhhf,
    const float* __restrict__ bihb, const float* __restrict__ bhhb)
{
    extern __shared__ char smem[];
    const u32 smem_u = s2u(smem);
    const int tid = threadIdx.x, lane = tid & 31, wid = tid >> 5;
    const int wm = wid >> 2, wn = wid & 3;
    const int c0 = blockIdx.x * 128, r0 = blockIdx.y * 128, dir = blockIdx.z;

    const __half* __restrict__ Ax = g_x16 + (size_t)r0 * HH;
    const __half* __restrict__ Bw = g_Wih16 + ((size_t)dir * G4 + c0) * HH;

    float acc[4][4][4];
#pragma unroll
    for (int mi = 0; mi < 4; mi++)
#pragma unroll
        for (int nj = 0; nj < 4; nj++)
#pragma unroll
            for (int q = 0; q < 4; q++) acc[mi][nj][q] = 0.f;

#define PC_LOAD(st, buf) do { \
    int ko_ = (st) * 32; \
    u32 ab_ = smem_u + (buf) * PC_STAGE; \
    _Pragma("unroll") \
    for (int it = 0; it < 2; it++) { \
        int id = it * 256 + tid, row = id >> 2, c = id & 3; \
        cpa16(ab_ + row * 80 + c * 16, Ax + (size_t)row * HH + ko_ + c * 8); \
    } \
    u32 bb_ = ab_ + 10240; \
    _Pragma("unroll") \
    for (int it = 0; it < 2; it++) { \
        int id = it * 256 + tid, row = id >> 2, c = id & 3; \
        cpa16(bb_ + row * 80 + c * 16, Bw + (size_t)row * HH + ko_ + c * 8); \
    } \
} while (0)

    PC_LOAD(0, 0); CP_COMMIT;
    PC_LOAD(1, 1); CP_COMMIT;
    for (int st = 0; st < 32; st++) {
        CP_WAIT1;
        __syncthreads();
        if (st + 2 < 32) { int bf = (st + 2) % 3; PC_LOAD(st + 2, bf); }
        CP_COMMIT;
        const u32 abase = smem_u + (st % 3) * PC_STAGE;
        const u32 bbase = abase + 10240;
#pragma unroll
        for (int kk = 0; kk < 2; kk++) {
            u32 a[4][4];
#pragma unroll
            for (int mi = 0; mi < 4; mi++) {
                int row = wm * 64 + mi * 16 + (lane & 15);
                ldsm4(a[mi][0], a[mi][1], a[mi][2], a[mi][3],
                      abase + row * 80 + kk * 32 + (lane >> 4) * 16);
            }
            u32 b_[4][2];
#pragma unroll
            for (int nj2 = 0; nj2 < 2; nj2++) {
                int row = wn * 32 + nj2 * 16 + (lane & 7) + ((lane >> 4) << 3);
                u32 r0v, r1v, r2v, r3v;
                ldsm4(r0v, r1v, r2v, r3v,
                      bbase + row * 80 + kk * 32 + ((lane >> 3) & 1) * 16);
                b_[nj2 * 2][0] = r0v; b_[nj2 * 2][1] = r1v;
                b_[nj2 * 2 + 1][0] = r2v; b_[nj2 * 2 + 1][1] = r3v;
            }
#pragma unroll
            for (int mi = 0; mi < 4; mi++)
#pragma unroll
                for (int nj = 0; nj < 4; nj++)
                    mma16816(acc[mi][nj], a[mi], b_[nj]);
        }
    }
#undef PC_LOAD

    const float* bi = dir ? bihb : bihf;
    const float* bh = dir ? bhhb : bhhf;
#pragma unroll
    for (int nj = 0; nj < 4; nj++) {
        int n = c0 + wn * 32 + nj * 8 + (lane & 3) * 2;
        float bz0 = bi[n] + bh[n];
        float bz1 = bi[n + 1] + bh[n + 1];
#pragma unroll
        for (int mi = 0; mi < 4; mi++)
#pragma unroll
            for (int hrow = 0; hrow < 2; hrow++) {
                int m = wm * 64 + mi * 16 + (lane >> 2) + hrow * 8;
                int r = r0 + m, t = r & (TT - 1), bb2 = r >> 8;
                __half* dst = g_pre16 + (((size_t)dir * TT + t) * BB + bb2) * G4 + n;
                *(__half2*)dst = __halves2half2(
                    __float2half_rn(acc[mi][nj][hrow * 2 + 0] + bz0),
                    __float2half_rn(acc[mi][nj][hrow * 2 + 1] + bz1));
            }
    }
}

// ============================================================
// Persistent fused LSTM. 128 CTAs (64 j-tiles x 2 dirs), 1/SM.
// W_hh slice (64 gate-cols x 1024 k fp16) RESIDENT in smem.
// Per step: stream h16 (M=64 N=64 K=1024, 8 stages of 128k) ->
// gates -> pointwise (MUFU). c in regs. red.release/ld.acquire barrier.
// pre tile fp16, double-buffered, prefetched ONE FULL STEP ahead.
// smem: W 132096 | A 3x17408 | gates 64x68 f32 | pre 2x(64x72 fp16)
// ============================================================
#define W_STR 2064
#define A_OFF 132096
#define A_STAGE 17408
#define GATES_OFF 184320
#define PRE_OFF 201728
#define PRE_BUF 9216
#define ST_SMEM 220160

__global__ __launch_bounds__(256, 1) void step_persist(
    const int* __restrict__ mask, const float* __restrict__ h0,
    float* __restrict__ out)
{
    extern __shared__ char smem[];
    const u32 smem_u = s2u(smem);
    const int tid = threadIdx.x, lane = tid & 31, wid = tid >> 5;
    const int wm = wid >> 1, wn = wid & 1;
    const int j0 = blockIdx.x * 16, dir = blockIdx.y;

    // ---- load resident W (64 gate-cols x 1024 k fp16) + pre(0) ----
    {
        const __half* W = g_Whh16 + (size_t)dir * G4 * HH;
#pragma unroll
        for (int it = 0; it < 32; it++) {
            int id = it * 256 + tid;
            int row = id >> 7, c = id & 127;       // row: gate-col, c: 16B chunk
            int grp = row >> 4, jj = row & 15;
            cpa16(smem_u + row * W_STR + c * 16,
                  W + (size_t)(grp * HH + j0 + jj) * HH + c * 8);
        }
        // pre(0) into buf 0
        int t0 = dir ? (TT - 1) : 0;
        const __half* pg = g_pre16 + ((size_t)dir * TT + t0) * BB * G4;
#pragma unroll
        for (int it = 0; it < 2; it++) {
            int id = it * 256 + tid;
            int b = id >> 3, seg = (id >> 1) & 3, q = id & 1;
            cpa16(smem_u + PRE_OFF + b * 144 + seg * 32 + q * 16,
                  pg + (size_t)b * G4 + seg * HH + j0 + q * 8);
        }
        CP_COMMIT;
    }

    // ---- per-thread persistent state ----
    float h0c[4], creg[4];
#pragma unroll
    for (int it = 0; it < 4; it++) {
        int id = it * 256 + tid;
        int b = id >> 4, jj = id & 15;
        h0c[it] = h0[b * HH + j0 + jj];
        creg[it] = h0c[it];
    }

    float* gates = (float*)(smem + GATES_OFF);

    for (int s = 0; s < TT; s++) {
        const int pp = s & 1;
        const int t = dir ? (TT - 1 - s) : s;
        const __half* __restrict__ Ah = g_h16[dir][pp];
        const __half* presm = (const __half*)(smem + PRE_OFF + (s & 1) * PRE_BUF);

        float acc[4][4];
#pragma unroll
        for (int nj = 0; nj < 4; nj++)
#pragma unroll
            for (int q = 0; q < 4; q++) acc[nj][q] = 0.f;

#define ST_LOAD(st, buf) do { \
    int ko_ = (st) * 128; \
    u32 ab_ = smem_u + A_OFF + (buf) * A_STAGE; \
    _Pragma("unroll") \
    for (int it = 0; it < 4; it++) { \
        int id = it * 256 + tid, row = id >> 4, c = id & 15; \
        cpa16(ab_ + row * 272 + c * 16, Ah + (size_t)row * HH + ko_ + c * 8); \
    } \
} while (0)

        ST_LOAD(0, 0); CP_COMMIT;
        ST_LOAD(1, 1); CP_COMMIT;

        // mask prefetch into regs (issues early, consumed at pointwise)
        float mreg[4];
#pragma unroll
        for (int it = 0; it < 4; it++) {
            int id = it * 256 + tid, b = id >> 4;
            mreg[it] = (float)__ldg(&mask[b * TT + t]);
        }

        for (int st = 0; st < 8; st++) {
            CP_WAIT1;
            __syncthreads();
            if (st + 2 < 8) { int bf = (st + 2) % 3; ST_LOAD(st + 2, bf); }
            if (st == 0 && s + 1 < TT) {
                // prefetch pre(s+1) into the other buffer (rides L2's group)
                int tn = dir ? (TT - 2 - s) : (s + 1);
                const __half* pg = g_pre16 + ((size_t)dir * TT + tn) * BB * G4;
                u32 pb = smem_u + PRE_OFF + ((s + 1) & 1) * PRE_BUF;
#pragma unroll
                for (int it = 0; it < 2; it++) {
                    int id = it * 256 + tid;
                    int b = id >> 3, seg = (id >> 1) & 3, q = id & 1;
                    cpa16(pb + b * 144 + seg * 32 + q * 16,
                          pg + (size_t)b * G4 + seg * HH + j0 + q * 8);
                }
            }
            CP_COMMIT;
            const u32 abase = smem_u + A_OFF + (st % 3) * A_STAGE;
            const u32 wkoff = st * 256;
#pragma unroll
            for (int kk = 0; kk < 8; kk++) {
                u32 a[4];
                {
                    int row = wm * 16 + (lane & 15);
                    ldsm4(a[0], a[1], a[2], a[3],
                          abase + row * 272 + kk * 32 + (lane >> 4) * 16);
                }
                u32 b_[4][2];
#pragma unroll
                for (int nj2 = 0; nj2 < 2; nj2++) {
                    int row = wn * 32 + nj2 * 16 + (lane & 7) + ((lane >> 4) << 3);
                    u32 r0, r1, r2, r3;
                    ldsm4(r0, r1, r2, r3,
                          smem_u + row * W_STR + wkoff + kk * 32 + ((lane >> 3) & 1) * 16);
                    b_[nj2 * 2][0] = r0; b_[nj2 * 2][1] = r1;
                    b_[nj2 * 2 + 1][0] = r2; b_[nj2 * 2 + 1][1] = r3;
                }
#pragma unroll
                for (int nj = 0; nj < 4; nj++)
                    mma16816(acc[nj], a, b_[nj]);   // h16 * W16
            }
        }
#undef ST_LOAD

        // ---- write gate tile to smem ----
#pragma unroll
        for (int nj = 0; nj < 4; nj++) {
            int n = wn * 32 + nj * 8 + (lane & 3) * 2;
            int m = wm * 16 + (lane >> 2);
            *(float2*)&gates[m * 68 + n]       = make_float2(acc[nj][0], acc[nj][1]);
            *(float2*)&gates[(m + 8) * 68 + n] = make_float2(acc[nj][2], acc[nj][3]);
        }
        __syncthreads();

        // ---- pointwise: 4 outputs/thread; write h (needed by others) first ----
        float hnv[4];
#pragma unroll
        for (int it = 0; it < 4; it++) {
            int id = it * 256 + tid;
            int b = id >> 4, jj = id & 15;
            int j = j0 + jj;
            float gi = gates[b * 68 + jj]      + __half2float(presm[b * 72 + jj]);
            float gf = gates[b * 68 + 16 + jj] + __half2float(presm[b * 72 + 16 + jj]);
            float gg = gates[b * 68 + 32 + jj] + __half2float(presm[b * 72 + 32 + jj]);
            float go = gates[b * 68 + 48 + jj] + __half2float(presm[b * 72 + 48 + jj]);
            float iv = fsig(gi);
            float fv = fsig(gf);
            float gv = ftanh(gg);
            float ov = fsig(go);
            float cn = fv * creg[it] + iv * gv;
            float hn = ov * ftanh(cn);
            float m = mreg[it];
            float hz = h0c[it];
            hn = hn * m + hz * (1.f - m);
            cn = cn * m + hz * (1.f - m);
            creg[it] = cn;
            hnv[it] = hn;
            g_h16[dir][pp ^ 1][b * HH + j] = __float2half_rn(hn);
        }

        // ---- release h, arrive on per-dir barrier (release-atomic) ----
        __syncthreads();
        if (tid == 0) red_release_add(&g_bar2[dir], 1u);

        // ---- deferred output writes (overlap other CTAs' arrival) ----
#pragma unroll
        for (int it = 0; it < 4; it++) {
            int id = it * 256 + tid;
            int b = id >> 4, jj = id & 15;
            int j = j0 + jj;
            // outputs stacked in ITERATION order for both directions (per reference)
            out[((size_t)s * BB + b) * (2 * HH) + (size_t)dir * HH + j] = hnv[it];
            if (s == TT - 1) {
                out[OUT_Y + (size_t)b * (2 * HH) + (size_t)dir * HH + j] = hnv[it];
                out[OUT_Y + (size_t)BB * 2 * HH + (size_t)b * (2 * HH) + (size_t)dir * HH + j] = creg[it];
            }
        }

        if (s < TT - 1) {
            if (tid == 0) {
                unsigned int target = 64u * (s + 1);
                while (ld_acq(&g_bar2[dir]) < target) { }
            }
            __syncthreads();
        }
    }
}

// ---------------- host ----------------
extern "C" void kernel_launch(void* const* d_in, const int* in_sizes, int n_in,
                              void* d_out, int out_size) {
    const float* x    = (const float*)d_in[0];
    const int*   mask = (const int*)  d_in[1];
    const float* h0   = (const float*)d_in[2];
    const float* Wihf = (const float*)d_in[3];
    const float* Whhf = (const float*)d_in[4];
    const float* bihf = (const float*)d_in[5];
    const float* bhhf = (const float*)d_in[6];
    const float* Wihb = (const float*)d_in[7];
    const float* Whhb = (const float*)d_in[8];
    const float* bihb = (const float*)d_in[9];
    const float* bhhb = (const float*)d_in[10];
    float* out = (float*)d_out;

    cudaFuncSetAttribute(precompute_mma, cudaFuncAttributeMaxDynamicSharedMemorySize, 3 * PC_STAGE);
    cudaFuncSetAttribute(step_persist,   cudaFuncAttributeMaxDynamicSharedMemorySize, ST_SMEM);

    const size_t WOFF = (size_t)G4 * HH;
    to_fp16<<<8192, 256>>>(Wihf, 0, 0,    2097152);
    to_fp16<<<8192, 256>>>(Wihb, 0, WOFF, 2097152);
    to_fp16<<<8192, 256>>>(Whhf, 1, 0,    2097152);
    to_fp16<<<8192, 256>>>(Whhb, 1, WOFF, 2097152);
    to_fp16<<<32768, 256>>>(x,   2, 0,    8388608);
    init_state<<<(BB * HH) / 256, 256>>>(h0);

    precompute_mma<<<dim3(32, 128, 2), 256, 3 * PC_STAGE>>>(bihf, bhhf, bihb, bhhb);

    step_persist<<<dim3(64, 2), 256, ST_SMEM>>>(mask, h0, out);
}

// round 13
// speedup vs baseline: 3.3475x; 1.0297x over previous
#include <cuda_runtime.h>
#include <cuda_fp16.h>
#include <math.h>

#define TT 256
#define BB 64
#define HH 1024
#define G4 4096
#define OUT_Y ((size_t)TT * BB * 2 * HH)

typedef unsigned int u32;

// ---------------- scratch ----------------
__device__ __half g_pre16[(size_t)2 * TT * BB * G4];       // 256MB
__device__ __half g_h16[2][2][BB * HH];                    // ping-pong h (fp16)
__device__ __half g_Wih16[(size_t)2 * G4 * HH];
__device__ __half g_Whh16[(size_t)2 * G4 * HH];
__device__ __half g_x16[(size_t)TT * BB * HH];
__device__ unsigned int g_bar2[2];

// ---------------- PTX helpers ----------------
__device__ __forceinline__ u32 s2u(const void* p) {
    u32 a;
    asm("{ .reg .u64 t; cvta.to.shared.u64 t, %1; cvt.u32.u64 %0, t; }" : "=r"(a) : "l"(p));
    return a;
}
__device__ __forceinline__ void cpa16(u32 d, const void* s) {
    asm volatile("cp.async.cg.shared.global [%0], [%1], 16;" :: "r"(d), "l"(s));
}
#define CP_COMMIT asm volatile("cp.async.commit_group;" ::: "memory")
#define CP_WAIT1  asm volatile("cp.async.wait_group 1;" ::: "memory")

__device__ __forceinline__ void ldsm4(u32& r0, u32& r1, u32& r2, u32& r3, u32 a) {
    asm volatile("ldmatrix.sync.aligned.m8n8.x4.shared.b16 {%0,%1,%2,%3}, [%4];"
                 : "=r"(r0), "=r"(r1), "=r"(r2), "=r"(r3) : "r"(a));
}
__device__ __forceinline__ void mma16816(float* c, const u32* a, const u32* b) {
    asm volatile(
        "mma.sync.aligned.m16n8k16.row.col.f32.f16.f16.f32 "
        "{%0,%1,%2,%3}, {%4,%5,%6,%7}, {%8,%9}, {%0,%1,%2,%3};"
        : "+f"(c[0]), "+f"(c[1]), "+f"(c[2]), "+f"(c[3])
        : "r"(a[0]), "r"(a[1]), "r"(a[2]), "r"(a[3]), "r"(b[0]), "r"(b[1]));
}
__device__ __forceinline__ u32 ld_acq(const unsigned int* p) {
    u32 v;
    asm volatile("ld.acquire.gpu.u32 %0, [%1];" : "=r"(v) : "l"(p) : "memory");
    return v;
}
__device__ __forceinline__ void red_release_add(unsigned int* p, u32 v) {
    asm volatile("red.release.gpu.global.add.u32 [%0], %1;" :: "l"(p), "r"(v) : "memory");
}
// fast sigmoid/tanh via MUFU (err ~1e-6, independent of harness math flags)
__device__ __forceinline__ float fsig(float x) {
    float t, r;
    asm("ex2.approx.ftz.f32 %0, %1;" : "=f"(t) : "f"(-x * 1.442695041f));
    asm("rcp.approx.ftz.f32 %0, %1;" : "=f"(r) : "f"(1.f + t));
    return r;
}
__device__ __forceinline__ float ftanh(float x) {
    float t, r;
    asm("ex2.approx.ftz.f32 %0, %1;" : "=f"(t) : "f"(x * 2.885390082f));  // e^{2x}
    asm("rcp.approx.ftz.f32 %0, %1;" : "=f"(r) : "f"(1.f + t));
    return 1.f - 2.f * r;
}

// ---------------- convert / init ----------------
__global__ void to_fp16(const float* __restrict__ src, int sel, size_t off, int n2) {
    int i = blockIdx.x * 256 + threadIdx.x;
    if (i >= n2) return;
    float2 v = ((const float2*)src)[i];
    __half* dst = (sel == 0) ? g_Wih16 : (sel == 1) ? g_Whh16 : g_x16;
    ((__half2*)(dst + off))[i] =
        __halves2half2(__float2half_rn(v.x), __float2half_rn(v.y));
}

__global__ void init_state(const float* __restrict__ h0) {
    int i = blockIdx.x * blockDim.x + threadIdx.x;  // BB*HH threads
    if (i == 0) { g_bar2[0] = 0; g_bar2[1] = 0; }
    __half hb = __float2half_rn(h0[i]);
    g_h16[0][0][i] = hb; g_h16[1][0][i] = hb;
}

// ============================================================
// Precompute: g_pre16 = fp16(x16 @ W_ih16^T + b_ih + b_hh)
// Block: M=128 rows (r=b*T+t), N=128 gate cols, K=1024 (32 stages of 32).
// 8 warps: wm=wid>>2 (M64), wn=wid&3 (N32). Warp tile 64x32.
// ============================================================
#define PC_STAGE 20480
__global__ __launch_bounds__(256, 2) void precompute_mma(
    const float* __restrict__ bihf, const float* __restrict__ bhhf,
    const float* __restrict__ bihb, const float* __restrict__ bhhb)
{
    extern __shared__ char smem[];
    const u32 smem_u = s2u(smem);
    const int tid = threadIdx.x, lane = tid & 31, wid = tid >> 5;
    const int wm = wid >> 2, wn = wid & 3;
    const int c0 = blockIdx.x * 128, r0 = blockIdx.y * 128, dir = blockIdx.z;

    const __half* __restrict__ Ax = g_x16 + (size_t)r0 * HH;
    const __half* __restrict__ Bw = g_Wih16 + ((size_t)dir * G4 + c0) * HH;

    float acc[4][4][4];
#pragma unroll
    for (int mi = 0; mi < 4; mi++)
#pragma unroll
        for (int nj = 0; nj < 4; nj++)
#pragma unroll
            for (int q = 0; q < 4; q++) acc[mi][nj][q] = 0.f;

#define PC_LOAD(st, buf) do { \
    int ko_ = (st) * 32; \
    u32 ab_ = smem_u + (buf) * PC_STAGE; \
    _Pragma("unroll") \
    for (int it = 0; it < 2; it++) { \
        int id = it * 256 + tid, row = id >> 2, c = id & 3; \
        cpa16(ab_ + row * 80 + c * 16, Ax + (size_t)row * HH + ko_ + c * 8); \
    } \
    u32 bb_ = ab_ + 10240; \
    _Pragma("unroll") \
    for (int it = 0; it < 2; it++) { \
        int id = it * 256 + tid, row = id >> 2, c = id & 3; \
        cpa16(bb_ + row * 80 + c * 16, Bw + (size_t)row * HH + ko_ + c * 8); \
    } \
} while (0)

    PC_LOAD(0, 0); CP_COMMIT;
    PC_LOAD(1, 1); CP_COMMIT;
    for (int st = 0; st < 32; st++) {
        CP_WAIT1;
        __syncthreads();
        if (st + 2 < 32) { int bf = (st + 2) % 3; PC_LOAD(st + 2, bf); }
        CP_COMMIT;
        const u32 abase = smem_u + (st % 3) * PC_STAGE;
        const u32 bbase = abase + 10240;
#pragma unroll
        for (int kk = 0; kk < 2; kk++) {
            u32 a[4][4];
#pragma unroll
            for (int mi = 0; mi < 4; mi++) {
                int row = wm * 64 + mi * 16 + (lane & 15);
                ldsm4(a[mi][0], a[mi][1], a[mi][2], a[mi][3],
                      abase + row * 80 + kk * 32 + (lane >> 4) * 16);
            }
            u32 b_[4][2];
#pragma unroll
            for (int nj2 = 0; nj2 < 2; nj2++) {
                int row = wn * 32 + nj2 * 16 + (lane & 7) + ((lane >> 4) << 3);
                u32 r0v, r1v, r2v, r3v;
                ldsm4(r0v, r1v, r2v, r3v,
                      bbase + row * 80 + kk * 32 + ((lane >> 3) & 1) * 16);
                b_[nj2 * 2][0] = r0v; b_[nj2 * 2][1] = r1v;
                b_[nj2 * 2 + 1][0] = r2v; b_[nj2 * 2 + 1][1] = r3v;
            }
#pragma unroll
            for (int mi = 0; mi < 4; mi++)
#pragma unroll
                for (int nj = 0; nj < 4; nj++)
                    mma16816(acc[mi][nj], a[mi], b_[nj]);
        }
    }
#undef PC_LOAD

    const float* bi = dir ? bihb : bihf;
    const float* bh = dir ? bhhb : bhhf;
#pragma unroll
    for (int nj = 0; nj < 4; nj++) {
        int n = c0 + wn * 32 + nj * 8 + (lane & 3) * 2;
        float bz0 = bi[n] + bh[n];
        float bz1 = bi[n + 1] + bh[n + 1];
#pragma unroll
        for (int mi = 0; mi < 4; mi++)
#pragma unroll
            for (int hrow = 0; hrow < 2; hrow++) {
                int m = wm * 64 + mi * 16 + (lane >> 2) + hrow * 8;
                int r = r0 + m, t = r & (TT - 1), bb2 = r >> 8;
                __half* dst = g_pre16 + (((size_t)dir * TT + t) * BB + bb2) * G4 + n;
                *(__half2*)dst = __halves2half2(
                    __float2half_rn(acc[mi][nj][hrow * 2 + 0] + bz0),
                    __float2half_rn(acc[mi][nj][hrow * 2 + 1] + bz1));
            }
    }
}

// ============================================================
// Persistent fused LSTM. 128 CTAs (64 j-tiles x 2 dirs), 1/SM.
// W_hh slice (64 gate-cols x 1024 k fp16) RESIDENT in smem.
// Step GEMM: K-SPLIT warp layout — warps 0-3 (k-half 0) and 4-7 (k-half 1)
// each compute the full 64x64 tile at M32xN32/warp over their 64k per stage
// => 2 smem wavefronts per mma (was 3). Partial sums folded in pointwise.
// gatesB (half-1 partials) reuses A pipeline buffer 0 (dead by epilogue).
// smem: W 132096 | A 3x17408 (buf0 doubles as gatesB) | gatesA | pre 2x
// ============================================================
#define W_STR 2064
#define A_OFF 132096
#define A_STAGE 17408
#define GATES_OFF 184320
#define PRE_OFF 201728
#define PRE_BUF 9216
#define ST_SMEM 220160

__global__ __launch_bounds__(256, 1) void step_persist(
    const int* __restrict__ mask, const float* __restrict__ h0,
    float* __restrict__ out)
{
    extern __shared__ char smem[];
    const u32 smem_u = s2u(smem);
    const int tid = threadIdx.x, lane = tid & 31, wid = tid >> 5;
    const int wk = wid >> 2;            // k-half
    const int wq = wid & 3;
    const int wm = wq >> 1, wn = wq & 1;  // M32 x N32 warp tile
    const int j0 = blockIdx.x * 16, dir = blockIdx.y;

    // ---- load resident W (64 gate-cols x 1024 k fp16) + pre(0) ----
    {
        const __half* W = g_Whh16 + (size_t)dir * G4 * HH;
#pragma unroll
        for (int it = 0; it < 32; it++) {
            int id = it * 256 + tid;
            int row = id >> 7, c = id & 127;       // row: gate-col, c: 16B chunk
            int grp = row >> 4, jj = row & 15;
            cpa16(smem_u + row * W_STR + c * 16,
                  W + (size_t)(grp * HH + j0 + jj) * HH + c * 8);
        }
        // pre(0) into buf 0
        int t0 = dir ? (TT - 1) : 0;
        const __half* pg = g_pre16 + ((size_t)dir * TT + t0) * BB * G4;
#pragma unroll
        for (int it = 0; it < 2; it++) {
            int id = it * 256 + tid;
            int b = id >> 3, seg = (id >> 1) & 3, q = id & 1;
            cpa16(smem_u + PRE_OFF + b * 144 + seg * 32 + q * 16,
                  pg + (size_t)b * G4 + seg * HH + j0 + q * 8);
        }
        CP_COMMIT;
    }

    // ---- per-thread persistent state ----
    float h0c[4], creg[4];
#pragma unroll
    for (int it = 0; it < 4; it++) {
        int id = it * 256 + tid;
        int b = id >> 4, jj = id & 15;
        h0c[it] = h0[b * HH + j0 + jj];
        creg[it] = h0c[it];
    }

    float* gatesA = (float*)(smem + GATES_OFF);
    float* gatesB = (float*)(smem + A_OFF);     // reuses A buf0 in epilogue

    for (int s = 0; s < TT; s++) {
        const int pp = s & 1;
        const int t = dir ? (TT - 1 - s) : s;
        const __half* __restrict__ Ah = g_h16[dir][pp];
        const __half* presm = (const __half*)(smem + PRE_OFF + (s & 1) * PRE_BUF);

        float acc[2][4][4];
#pragma unroll
        for (int mi = 0; mi < 2; mi++)
#pragma unroll
            for (int nj = 0; nj < 4; nj++)
#pragma unroll
                for (int q = 0; q < 4; q++) acc[mi][nj][q] = 0.f;

#define ST_LOAD(st, buf) do { \
    int ko_ = (st) * 128; \
    u32 ab_ = smem_u + A_OFF + (buf) * A_STAGE; \
    _Pragma("unroll") \
    for (int it = 0; it < 4; it++) { \
        int id = it * 256 + tid, row = id >> 4, c = id & 15; \
        cpa16(ab_ + row * 272 + c * 16, Ah + (size_t)row * HH + ko_ + c * 8); \
    } \
} while (0)

        ST_LOAD(0, 0); CP_COMMIT;
        ST_LOAD(1, 1); CP_COMMIT;

        // mask prefetch into regs (issues early, consumed at pointwise)
        float mreg[4];
#pragma unroll
        for (int it = 0; it < 4; it++) {
            int id = it * 256 + tid, b = id >> 4;
            mreg[it] = (float)__ldg(&mask[b * TT + t]);
        }

        for (int st = 0; st < 8; st++) {
            CP_WAIT1;
            __syncthreads();
            if (st + 2 < 8) { int bf = (st + 2) % 3; ST_LOAD(st + 2, bf); }
            if (st == 0 && s + 1 < TT) {
                // prefetch pre(s+1) into the other buffer (rides this group)
                int tn = dir ? (TT - 2 - s) : (s + 1);
                const __half* pg = g_pre16 + ((size_t)dir * TT + tn) * BB * G4;
                u32 pb = smem_u + PRE_OFF + ((s + 1) & 1) * PRE_BUF;
#pragma unroll
                for (int it = 0; it < 2; it++) {
                    int id = it * 256 + tid;
                    int b = id >> 3, seg = (id >> 1) & 3, q = id & 1;
                    cpa16(pb + b * 144 + seg * 32 + q * 16,
                          pg + (size_t)b * G4 + seg * HH + j0 + q * 8);
                }
            }
            CP_COMMIT;
            const u32 abase = smem_u + A_OFF + (st % 3) * A_STAGE + wk * 128;
            const u32 wbase = smem_u + st * 256 + wk * 128;
#pragma unroll
            for (int kk = 0; kk < 4; kk++) {        // 64k per half per stage
                u32 a[2][4];
#pragma unroll
                for (int mi = 0; mi < 2; mi++) {
                    int row = wm * 32 + mi * 16 + (lane & 15);
                    ldsm4(a[mi][0], a[mi][1], a[mi][2], a[mi][3],
                          abase + row * 272 + kk * 32 + (lane >> 4) * 16);
                }
                u32 b_[4][2];
#pragma unroll
                for (int nj2 = 0; nj2 < 2; nj2++) {
                    int row = wn * 32 + nj2 * 16 + (lane & 7) + ((lane >> 4) << 3);
                    u32 r0, r1, r2, r3;
                    ldsm4(r0, r1, r2, r3,
                          wbase + row * W_STR + kk * 32 + ((lane >> 3) & 1) * 16);
                    b_[nj2 * 2][0] = r0; b_[nj2 * 2][1] = r1;
                    b_[nj2 * 2 + 1][0] = r2; b_[nj2 * 2 + 1][1] = r3;
                }
#pragma unroll
                for (int mi = 0; mi < 2; mi++)
#pragma unroll
                    for (int nj = 0; nj < 4; nj++)
                        mma16816(acc[mi][nj], a[mi], b_[nj]);   // h16 * W16
            }
        }
#undef ST_LOAD

        // ---- write partial gate tiles (half 0 -> gatesA, half 1 -> gatesB) ----
        __syncthreads();   // all buf0 reads (st=6 compute) done before gatesB write
        {
            float* gbuf = wk ? gatesB : gatesA;
#pragma unroll
            for (int nj = 0; nj < 4; nj++) {
                int n = wn * 32 + nj * 8 + (lane & 3) * 2;
#pragma unroll
                for (int mi = 0; mi < 2; mi++) {
                    int m = wm * 32 + mi * 16 + (lane >> 2);
                    *(float2*)&gbuf[m * 68 + n] =
                        make_float2(acc[mi][nj][0], acc[mi][nj][1]);
                    *(float2*)&gbuf[(m + 8) * 68 + n] =
                        make_float2(acc[mi][nj][2], acc[mi][nj][3]);
                }
            }
        }
        __syncthreads();

        // ---- pointwise: 4 outputs/thread; write h (needed by others) first ----
        float hnv[4];
#pragma unroll
        for (int it = 0; it < 4; it++) {
            int id = it * 256 + tid;
            int b = id >> 4, jj = id & 15;
            int j = j0 + jj;
            float gi = gatesA[b * 68 + jj]      + gatesB[b * 68 + jj]
                     + __half2float(presm[b * 72 + jj]);
            float gf = gatesA[b * 68 + 16 + jj] + gatesB[b * 68 + 16 + jj]
                     + __half2float(presm[b * 72 + 16 + jj]);
            float gg = gatesA[b * 68 + 32 + jj] + gatesB[b * 68 + 32 + jj]
                     + __half2float(presm[b * 72 + 32 + jj]);
            float go = gatesA[b * 68 + 48 + jj] + gatesB[b * 68 + 48 + jj]
                     + __half2float(presm[b * 72 + 48 + jj]);
            float iv = fsig(gi);
            float fv = fsig(gf);
            float gv = ftanh(gg);
            float ov = fsig(go);
            float cn = fv * creg[it] + iv * gv;
            float hn = ov * ftanh(cn);
            float m = mreg[it];
            float hz = h0c[it];
            hn = hn * m + hz * (1.f - m);
            cn = cn * m + hz * (1.f - m);
            creg[it] = cn;
            hnv[it] = hn;
            g_h16[dir][pp ^ 1][b * HH + j] = __float2half_rn(hn);
        }

        // ---- release h, arrive on per-dir barrier (release-atomic) ----
        __syncthreads();
        if (tid == 0) red_release_add(&g_bar2[dir], 1u);

        // ---- deferred output writes (overlap other CTAs' arrival) ----
#pragma unroll
        for (int it = 0; it < 4; it++) {
            int id = it * 256 + tid;
            int b = id >> 4, jj = id & 15;
            int j = j0 + jj;
            // outputs stacked in ITERATION order for both directions (per reference)
            out[((size_t)s * BB + b) * (2 * HH) + (size_t)dir * HH + j] = hnv[it];
            if (s == TT - 1) {
                out[OUT_Y + (size_t)b * (2 * HH) + (size_t)dir * HH + j] = hnv[it];
                out[OUT_Y + (size_t)BB * 2 * HH + (size_t)b * (2 * HH) + (size_t)dir * HH + j] = creg[it];
            }
        }

        if (s < TT - 1) {
            if (tid == 0) {
                unsigned int target = 64u * (s + 1);
                while (ld_acq(&g_bar2[dir]) < target) { }
            }
            __syncthreads();
        }
    }
}

// ---------------- host ----------------
extern "C" void kernel_launch(void* const* d_in, const int* in_sizes, int n_in,
                              void* d_out, int out_size) {
    const float* x    = (const float*)d_in[0];
    const int*   mask = (const int*)  d_in[1];
    const float* h0   = (const float*)d_in[2];
    const float* Wihf = (const float*)d_in[3];
    const float* Whhf = (const float*)d_in[4];
    const float* bihf = (const float*)d_in[5];
    const float* bhhf = (const float*)d_in[6];
    const float* Wihb = (const float*)d_in[7];
    const float* Whhb = (const float*)d_in[8];
    const float* bihb = (const float*)d_in[9];
    const float* bhhb = (const float*)d_in[10];
    float* out = (float*)d_out;

    cudaFuncSetAttribute(precompute_mma, cudaFuncAttributeMaxDynamicSharedMemorySize, 3 * PC_STAGE);
    cudaFuncSetAttribute(step_persist,   cudaFuncAttributeMaxDynamicSharedMemorySize, ST_SMEM);

    const size_t WOFF = (size_t)G4 * HH;
    to_fp16<<<8192, 256>>>(Wihf, 0, 0,    2097152);
    to_fp16<<<8192, 256>>>(Wihb, 0, WOFF, 2097152);
    to_fp16<<<8192, 256>>>(Whhf, 1, 0,    2097152);
    to_fp16<<<8192, 256>>>(Whhb, 1, WOFF, 2097152);
    to_fp16<<<32768, 256>>>(x,   2, 0,    8388608);
    init_state<<<(BB * HH) / 256, 256>>>(h0);

    precompute_mma<<<dim3(32, 128, 2), 256, 3 * PC_STAGE>>>(bihf, bhhf, bihb, bhhb);

    step_persist<<<dim3(64, 2), 256, ST_SMEM>>>(mask, h0, out);
}